// round 8
// baseline (speedup 1.0000x reference)
#include <cuda_runtime.h>
#include <cuda_bf16.h>
#include <cstdint>
#include <math.h>

constexpr int NB = 32;
constexpr int NC = 1024;
constexpr int NS = 1024;
constexpr size_t MAT = (size_t)NC * NS;           // 1M elems
constexpr size_t MB1 = 1u << 20;

// ---------------------------------------------------------------------------
// One big scratch buffer (device global — allocation-guard safe)
// ---------------------------------------------------------------------------
__device__ __align__(128) unsigned char g_buf[1040 * MB1];

#define OFF_XSH   (0 * 64 * MB1)
#define OFF_XSL   (1 * 64 * MB1)
#define OFF_XIH   (2 * 64 * MB1)
#define OFF_XIL   (3 * 64 * MB1)
#define OFF_QH    (4 * 64 * MB1)
#define OFF_QL    (5 * 64 * MB1)
#define OFF_KH    (6 * 64 * MB1)
#define OFF_KL    (7 * 64 * MB1)
#define OFF_VTH   (8 * 64 * MB1)
#define OFF_VTL   (9 * 64 * MB1)
#define OFF_WAH   (10 * 64 * MB1)
#define OFF_WAL   (11 * 64 * MB1)
#define OFF_NVTH  (12 * 64 * MB1)
#define OFF_NVTL  (13 * 64 * MB1)
#define OFF_SF32  (14 * 64 * MB1)                 // 128MB fp32 scores
#define OFF_W0    (16 * 64 * MB1)                 // 8 x 2MB weight hi/lo

// ---------------------------------------------------------------------------
// sm_80+-portable PTX helpers (NO tcgen05 — unavailable via compute_103 PTX)
// ---------------------------------------------------------------------------
__device__ __forceinline__ uint32_t smem_to_u32(const void* p) {
    uint32_t a;
    asm("{ .reg .u64 t; cvta.to.shared.u64 t, %1; cvt.u32.u64 %0, t; }" : "=r"(a) : "l"(p));
    return a;
}
__device__ __forceinline__ void cp16(uint32_t dst, const void* src) {
    asm volatile("cp.async.cg.shared.global [%0], [%1], 16;" :: "r"(dst), "l"(src) : "memory");
}
__device__ __forceinline__ void ldsm4(uint32_t* r, uint32_t addr) {
    asm volatile("ldmatrix.sync.aligned.m8n8.x4.shared.b16 {%0,%1,%2,%3}, [%4];"
        : "=r"(r[0]), "=r"(r[1]), "=r"(r[2]), "=r"(r[3]) : "r"(addr));
}
__device__ __forceinline__ void mma_bf16(float* c, const uint32_t* a, const uint32_t* b) {
    asm volatile(
        "mma.sync.aligned.m16n8k16.row.col.f32.bf16.bf16.f32 "
        "{%0,%1,%2,%3}, {%4,%5,%6,%7}, {%8,%9}, {%0,%1,%2,%3};"
        : "+f"(c[0]), "+f"(c[1]), "+f"(c[2]), "+f"(c[3])
        : "r"(a[0]), "r"(a[1]), "r"(a[2]), "r"(a[3]), "r"(b[0]), "r"(b[1]));
}

__device__ __forceinline__ void split_bf16(float v, __nv_bfloat16& h, __nv_bfloat16& l) {
    h = __float2bfloat16(v);
    l = __float2bfloat16(v - __bfloat162float(h));
}

enum { EPI_TANH = 0, EPI_TANH_T = 1, EPI_SCALE = 2, EPI_SPLIT_T = 3, EPI_BIASRES = 4 };

// GEMM tiling: CTA 128x256, warp 64x64 (8 warps 2x4), BK=32, 3-stage pipeline
constexpr int STAGES = 3;
constexpr int BK = 32;
constexpr int CHUNKS = NC / BK;                    // 32
constexpr int TPAD = 40;                           // padded row (bf16), 80B
constexpr int ATB = 128 * TPAD * 2;                // 10240 (A tile)
constexpr int BTB = 256 * TPAD * 2;                // 20480 (B tile)
constexpr int STAGE_BYTES = 2 * ATB + 2 * BTB;     // 61440
constexpr int SMEM_BYTES = STAGES * STAGE_BYTES;   // 184320

// ---------------------------------------------------------------------------
// Split-bf16 mma.sync GEMM:  D[m,n] = sum_k A[m,k]*B[n,k]  (both K-major)
// ---------------------------------------------------------------------------
template<int EPI, bool ABATCH>
__global__ __launch_bounds__(256, 1) void gemm_mma(
    const __nv_bfloat16* __restrict__ Ah, const __nv_bfloat16* __restrict__ Al,
    const __nv_bfloat16* __restrict__ Bh, const __nv_bfloat16* __restrict__ Bl,
    const float* __restrict__ bias, const float* __restrict__ resid,
    float* __restrict__ Of, __nv_bfloat16* __restrict__ Oh, __nv_bfloat16* __restrict__ Ol,
    float alpha)
{
    extern __shared__ char smem[];
    const uint32_t sb = smem_to_u32(smem);
    const int tid = threadIdx.x, lane = tid & 31, wid = tid >> 5;
    const int warp_m = wid & 1, warp_n = wid >> 1;        // 2 x 4
    const int bx = blockIdx.x, by = blockIdx.y, bz = blockIdx.z;
    const size_t bat = (size_t)bz * MAT;
    const int m0 = by * 128, n0 = bx * 256;

    const __nv_bfloat16* srcA_h = Ah + (ABATCH ? bat : 0);
    const __nv_bfloat16* srcA_l = Al + (ABATCH ? bat : 0);
    const __nv_bfloat16* srcB_h = Bh + bat;
    const __nv_bfloat16* srcB_l = Bl + bat;

    auto load_chunk = [&](int chunk, int stage) {
        const int k0 = chunk * BK;
        const uint32_t sbase = sb + stage * STAGE_BYTES;
        // A hi/lo: 128 rows x 32 k
        #pragma unroll
        for (int t = 0; t < 2; ++t) {
            int gi = tid + t * 256;                 // 0..511
            int r = gi >> 2, c8 = (gi & 3) * 8;
            uint32_t so = (uint32_t)(r * TPAD + c8) * 2;
            const size_t go = (size_t)(m0 + r) * 1024 + k0 + c8;
            cp16(sbase + so, srcA_h + go);
            cp16(sbase + ATB + so, srcA_l + go);
        }
        // B hi/lo: 256 rows x 32 k
        #pragma unroll
        for (int t = 0; t < 4; ++t) {
            int gi = tid + t * 256;                 // 0..1023
            int r = gi >> 2, c8 = (gi & 3) * 8;
            uint32_t so = (uint32_t)(r * TPAD + c8) * 2;
            const size_t go = (size_t)(n0 + r) * 1024 + k0 + c8;
            cp16(sbase + 2 * ATB + so, srcB_h + go);
            cp16(sbase + 2 * ATB + BTB + so, srcB_l + go);
        }
    };

    // prologue: stages 0,1
    load_chunk(0, 0);
    asm volatile("cp.async.commit_group;" ::: "memory");
    load_chunk(1, 1);
    asm volatile("cp.async.commit_group;" ::: "memory");

    float acc[4][8][4];
    #pragma unroll
    for (int mi = 0; mi < 4; ++mi)
        #pragma unroll
        for (int ni = 0; ni < 8; ++ni)
            #pragma unroll
            for (int e = 0; e < 4; ++e) acc[mi][ni][e] = 0.f;

    for (int c = 0; c < CHUNKS; ++c) {
        asm volatile("cp.async.wait_group 1;" ::: "memory");   // chunk c arrived
        __syncthreads();

        const int nc = c + STAGES - 1;
        if (nc < CHUNKS) load_chunk(nc, nc % STAGES);
        asm volatile("cp.async.commit_group;" ::: "memory");

        const uint32_t sbase = sb + (c % STAGES) * STAGE_BYTES;
        const uint32_t aHb = sbase, aLb = sbase + ATB;
        const uint32_t bHb = sbase + 2 * ATB, bLb = sbase + 2 * ATB + BTB;

        #pragma unroll
        for (int s16 = 0; s16 < 2; ++s16) {
            const int koff = s16 * 16;
            uint32_t ah[4][4], al[4][4], bh[4][4], bl[4][4];
            #pragma unroll
            for (int mi = 0; mi < 4; ++mi) {
                uint32_t ro = (uint32_t)((warp_m * 64 + mi * 16 + (lane & 15)) * TPAD) * 2
                            + (uint32_t)(koff + ((lane >> 4) << 3)) * 2;
                ldsm4(ah[mi], aHb + ro);
                ldsm4(al[mi], aLb + ro);
            }
            #pragma unroll
            for (int nj = 0; nj < 4; ++nj) {
                uint32_t ro = (uint32_t)((warp_n * 64 + nj * 16 + (lane & 7) + ((lane >> 4) << 3)) * TPAD) * 2
                            + (uint32_t)(koff + (((lane >> 3) & 1) << 3)) * 2;
                ldsm4(bh[nj], bHb + ro);
                ldsm4(bl[nj], bLb + ro);
            }
            #pragma unroll
            for (int mi = 0; mi < 4; ++mi)
                #pragma unroll
                for (int ni = 0; ni < 8; ++ni) {
                    const uint32_t* bhp = &bh[ni >> 1][(ni & 1) * 2];
                    const uint32_t* blp = &bl[ni >> 1][(ni & 1) * 2];
                    mma_bf16(acc[mi][ni], ah[mi], bhp);
                    mma_bf16(acc[mi][ni], ah[mi], blp);
                    mma_bf16(acc[mi][ni], al[mi], bhp);
                }
        }
    }

    // ------------------------------ epilogue -------------------------------
    const int erow = m0 + warp_m * 64;
    const int ecol = n0 + warp_n * 64;
    const int rl = lane >> 2, cl = (lane & 3) * 2;

    #pragma unroll
    for (int mi = 0; mi < 4; ++mi) {
        const int r0e = erow + mi * 16 + rl;           // rows r0e, r0e+8
        float b0 = 0.f, b1 = 0.f;
        if (EPI == EPI_TANH || EPI == EPI_TANH_T || EPI == EPI_BIASRES) {
            b0 = bias[r0e]; b1 = bias[r0e + 8];
        }
        #pragma unroll
        for (int ni = 0; ni < 8; ++ni) {
            const int c0e = ecol + ni * 8 + cl;
            float* a = acc[mi][ni];

            if (EPI == EPI_TANH) {
                float v00 = tanhf(a[0] + b0), v01 = tanhf(a[1] + b0);
                float v10 = tanhf(a[2] + b1), v11 = tanhf(a[3] + b1);
                __nv_bfloat16 h0, l0, h1, l1;
                split_bf16(v00, h0, l0); split_bf16(v01, h1, l1);
                __nv_bfloat162 ph{h0, h1}, pl{l0, l1};
                *(__nv_bfloat162*)(Oh + bat + (size_t)r0e * 1024 + c0e) = ph;
                *(__nv_bfloat162*)(Ol + bat + (size_t)r0e * 1024 + c0e) = pl;
                split_bf16(v10, h0, l0); split_bf16(v11, h1, l1);
                __nv_bfloat162 ph2{h0, h1}, pl2{l0, l1};
                *(__nv_bfloat162*)(Oh + bat + (size_t)(r0e + 8) * 1024 + c0e) = ph2;
                *(__nv_bfloat162*)(Ol + bat + (size_t)(r0e + 8) * 1024 + c0e) = pl2;
            } else if (EPI == EPI_TANH_T || EPI == EPI_SPLIT_T) {
                float v[4] = { a[0], a[1], a[2], a[3] };
                if (EPI == EPI_TANH_T) {
                    v[0] = tanhf(v[0] + b0); v[1] = tanhf(v[1] + b0);
                    v[2] = tanhf(v[2] + b1); v[3] = tanhf(v[3] + b1);
                }
                const int rr[4] = { r0e, r0e, r0e + 8, r0e + 8 };
                const int cc[4] = { c0e, c0e + 1, c0e, c0e + 1 };
                #pragma unroll
                for (int e = 0; e < 4; ++e) {
                    __nv_bfloat16 hh, ll;
                    split_bf16(v[e], hh, ll);
                    const size_t idx = bat + (size_t)cc[e] * 1024 + rr[e];
                    Oh[idx] = hh; Ol[idx] = ll;
                }
            } else if (EPI == EPI_SCALE) {
                float2 o0{a[0] * alpha, a[1] * alpha};
                float2 o1{a[2] * alpha, a[3] * alpha};
                *(float2*)(Of + bat + (size_t)r0e * 1024 + c0e) = o0;
                *(float2*)(Of + bat + (size_t)(r0e + 8) * 1024 + c0e) = o1;
            } else {  // EPI_BIASRES
                float2 r0v = *(const float2*)(resid + bat + (size_t)r0e * 1024 + c0e);
                float2 r1v = *(const float2*)(resid + bat + (size_t)(r0e + 8) * 1024 + c0e);
                float2 o0{a[0] + b0 + r0v.x, a[1] + b0 + r0v.y};
                float2 o1{a[2] + b1 + r1v.x, a[3] + b1 + r1v.y};
                *(float2*)(Of + bat + (size_t)r0e * 1024 + c0e) = o0;
                *(float2*)(Of + bat + (size_t)(r0e + 8) * 1024 + c0e) = o1;
            }
        }
    }
}

// ---------------------------------------------------------------------------
// fp32 -> bf16 hi/lo elementwise (weights)
// ---------------------------------------------------------------------------
__global__ __launch_bounds__(256) void split_k(const float* __restrict__ in,
                                               __nv_bfloat16* __restrict__ oh,
                                               __nv_bfloat16* __restrict__ ol) {
    size_t i = (size_t)blockIdx.x * 256 + threadIdx.x;
    float v = in[i];
    __nv_bfloat16 h, l;
    split_bf16(v, h, l);
    oh[i] = h; ol[i] = l;
}

// ---------------------------------------------------------------------------
// fp32 [B][C,S] -> transposed bf16 hi/lo [B][S,C]
// ---------------------------------------------------------------------------
__global__ __launch_bounds__(256) void transpose_split_k(
    const float* __restrict__ in, __nv_bfloat16* __restrict__ oh, __nv_bfloat16* __restrict__ ol) {
    __shared__ float t[32][33];
    const int tx = threadIdx.x, ty = threadIdx.y;   // 32x8
    const int s0 = blockIdx.x * 32, c0 = blockIdx.y * 32;
    const size_t bat = (size_t)blockIdx.z * MAT;
    #pragma unroll
    for (int i = 0; i < 4; ++i)
        t[ty + 8 * i][tx] = in[bat + (size_t)(c0 + ty + 8 * i) * 1024 + s0 + tx];
    __syncthreads();
    #pragma unroll
    for (int i = 0; i < 4; ++i) {
        float v = t[tx][ty + 8 * i];
        __nv_bfloat16 h, l;
        split_bf16(v, h, l);
        const size_t idx = bat + (size_t)(s0 + ty + 8 * i) * 1024 + c0 + tx;
        oh[idx] = h; ol[idx] = l;
    }
}

// ---------------------------------------------------------------------------
// Row softmax fp32 -> bf16 hi/lo weights
// ---------------------------------------------------------------------------
__global__ __launch_bounds__(256) void softmax_split_k(
    const float* __restrict__ data, __nv_bfloat16* __restrict__ oh, __nv_bfloat16* __restrict__ ol) {
    __shared__ float red[8];
    __shared__ float bval;
    const size_t row = blockIdx.x;
    const float* p = data + row * (size_t)NC;
    const int tid = threadIdx.x, lane = tid & 31, wid = tid >> 5;

    float4 v = ((const float4*)p)[tid];
    float mx = fmaxf(fmaxf(v.x, v.y), fmaxf(v.z, v.w));
    #pragma unroll
    for (int o = 16; o > 0; o >>= 1) mx = fmaxf(mx, __shfl_xor_sync(0xffffffffu, mx, o));
    if (lane == 0) red[wid] = mx;
    __syncthreads();
    if (tid < 32) {
        float t = (tid < 8) ? red[tid] : -INFINITY;
        #pragma unroll
        for (int o = 4; o > 0; o >>= 1) t = fmaxf(t, __shfl_xor_sync(0xffffffffu, t, o));
        if (tid == 0) bval = t;
    }
    __syncthreads();
    mx = bval;
    v.x = expf(v.x - mx); v.y = expf(v.y - mx);
    v.z = expf(v.z - mx); v.w = expf(v.w - mx);
    float s = (v.x + v.y) + (v.z + v.w);
    #pragma unroll
    for (int o = 16; o > 0; o >>= 1) s += __shfl_xor_sync(0xffffffffu, s, o);
    __syncthreads();
    if (lane == 0) red[wid] = s;
    __syncthreads();
    if (tid < 32) {
        float t = (tid < 8) ? red[tid] : 0.f;
        #pragma unroll
        for (int o = 4; o > 0; o >>= 1) t += __shfl_xor_sync(0xffffffffu, t, o);
        if (tid == 0) bval = t;
    }
    __syncthreads();
    const float inv = 1.f / bval;
    float vv[4] = {v.x * inv, v.y * inv, v.z * inv, v.w * inv};
    const size_t base = row * (size_t)NC + 4 * tid;
    #pragma unroll
    for (int j = 0; j < 4; ++j) {
        __nv_bfloat16 h, l;
        split_bf16(vv[j], h, l);
        oh[base + j] = h; ol[base + j] = l;
    }
}

// ---------------------------------------------------------------------------
extern "C" void kernel_launch(void* const* d_in, const int* in_sizes, int n_in,
                              void* d_out, int out_size)
{
    const float* shape_map = (const float*)d_in[0];
    const float* img_map   = (const float*)d_in[1];
    const float* wq = (const float*)d_in[2];
    const float* bq = (const float*)d_in[3];
    const float* wk = (const float*)d_in[4];
    const float* bk = (const float*)d_in[5];
    const float* wv = (const float*)d_in[6];
    const float* bv = (const float*)d_in[7];
    const float* wc = (const float*)d_in[8];
    const float* bc = (const float*)d_in[9];
    float* out = (float*)d_out;

    unsigned char* buf;
    cudaGetSymbolAddress((void**)&buf, g_buf);
    __nv_bfloat16* XSH = (__nv_bfloat16*)(buf + OFF_XSH);
    __nv_bfloat16* XSL = (__nv_bfloat16*)(buf + OFF_XSL);
    __nv_bfloat16* XIH = (__nv_bfloat16*)(buf + OFF_XIH);
    __nv_bfloat16* XIL = (__nv_bfloat16*)(buf + OFF_XIL);
    __nv_bfloat16* QH  = (__nv_bfloat16*)(buf + OFF_QH);
    __nv_bfloat16* QL  = (__nv_bfloat16*)(buf + OFF_QL);
    __nv_bfloat16* KH  = (__nv_bfloat16*)(buf + OFF_KH);
    __nv_bfloat16* KL  = (__nv_bfloat16*)(buf + OFF_KL);
    __nv_bfloat16* VTH = (__nv_bfloat16*)(buf + OFF_VTH);
    __nv_bfloat16* VTL = (__nv_bfloat16*)(buf + OFF_VTL);
    __nv_bfloat16* WAH = (__nv_bfloat16*)(buf + OFF_WAH);
    __nv_bfloat16* WAL = (__nv_bfloat16*)(buf + OFF_WAL);
    __nv_bfloat16* NVTH = (__nv_bfloat16*)(buf + OFF_NVTH);
    __nv_bfloat16* NVTL = (__nv_bfloat16*)(buf + OFF_NVTL);
    float* SF = (float*)(buf + OFF_SF32);
    __nv_bfloat16* W[8];   // qh,ql,kh,kl,vh,vl,ch,cl
    for (int i = 0; i < 8; ++i) W[i] = (__nv_bfloat16*)(buf + OFF_W0 + (size_t)i * 2 * MB1);

    cudaFuncSetAttribute(gemm_mma<EPI_TANH, false>,   cudaFuncAttributeMaxDynamicSharedMemorySize, SMEM_BYTES);
    cudaFuncSetAttribute(gemm_mma<EPI_TANH_T, false>, cudaFuncAttributeMaxDynamicSharedMemorySize, SMEM_BYTES);
    cudaFuncSetAttribute(gemm_mma<EPI_SCALE, true>,   cudaFuncAttributeMaxDynamicSharedMemorySize, SMEM_BYTES);
    cudaFuncSetAttribute(gemm_mma<EPI_SPLIT_T, true>, cudaFuncAttributeMaxDynamicSharedMemorySize, SMEM_BYTES);
    cudaFuncSetAttribute(gemm_mma<EPI_BIASRES, false>,cudaFuncAttributeMaxDynamicSharedMemorySize, SMEM_BYTES);

    const dim3 grid(NS / 256, NC / 128, NB);   // (4, 8, 32)

    // 0..2: wq split, shape transpose, GEMM Q
    split_k<<<MAT / 256, 256>>>(wq, W[0], W[1]);
    transpose_split_k<<<dim3(32, 32, NB), dim3(32, 8)>>>(shape_map, XSH, XSL);
    gemm_mma<EPI_TANH, false><<<grid, 256, SMEM_BYTES>>>(W[0], W[1], XSH, XSL, bq, nullptr, nullptr, QH, QL, 0.f);
    // 3..5: wk split, img transpose, GEMM K
    split_k<<<MAT / 256, 256>>>(wk, W[2], W[3]);
    transpose_split_k<<<dim3(32, 32, NB), dim3(32, 8)>>>(img_map, XIH, XIL);
    gemm_mma<EPI_TANH, false><<<grid, 256, SMEM_BYTES>>>(W[2], W[3], XIH, XIL, bk, nullptr, nullptr, KH, KL, 0.f);
    // 6..7: wv split, GEMM V (stored transposed [S,C])
    split_k<<<MAT / 256, 256>>>(wv, W[4], W[5]);
    gemm_mma<EPI_TANH_T, false><<<grid, 256, SMEM_BYTES>>>(W[4], W[5], XIH, XIL, bv, nullptr, nullptr, VTH, VTL, 0.f);
    // 8: wc split
    split_k<<<MAT / 256, 256>>>(wc, W[6], W[7]);
    // 9: scores = (Q @ K^T) / 32 -> fp32
    gemm_mma<EPI_SCALE, true><<<grid, 256, SMEM_BYTES>>>(QH, QL, KH, KL, nullptr, nullptr, SF, nullptr, nullptr, 0.03125f);
    // 10: softmax rows -> bf16 hi/lo
    softmax_split_k<<<NB * NC, 256>>>(SF, WAH, WAL);
    // 11: new_v = weights @ V (stored transposed [S,C])
    gemm_mma<EPI_SPLIT_T, true><<<grid, 256, SMEM_BYTES>>>(WAH, WAL, VTH, VTL, nullptr, nullptr, nullptr, NVTH, NVTL, 0.f);
    // 12: out = Wc @ new_v + bc + shape_map
    gemm_mma<EPI_BIASRES, false><<<grid, 256, SMEM_BYTES>>>(W[6], W[7], NVTH, NVTL, bc, shape_map, out, nullptr, nullptr, 0.f);
}

// round 9
// speedup vs baseline: 1.0130x; 1.0130x over previous
#include <cuda_runtime.h>
#include <cuda_bf16.h>
#include <cstdint>
#include <math.h>

constexpr int NB = 32;
constexpr int NC = 1024;
constexpr int NS = 1024;
constexpr size_t MAT = (size_t)NC * NS;           // 1M elems
constexpr size_t MB1 = 1u << 20;

// ---------------------------------------------------------------------------
// One big scratch buffer (device global — allocation-guard safe)
// ---------------------------------------------------------------------------
__device__ __align__(128) unsigned char g_buf[1040 * MB1];

#define OFF_XSH   (0 * 64 * MB1)
#define OFF_XSL   (1 * 64 * MB1)
#define OFF_XIH   (2 * 64 * MB1)
#define OFF_XIL   (3 * 64 * MB1)
#define OFF_QH    (4 * 64 * MB1)
#define OFF_QL    (5 * 64 * MB1)
#define OFF_KH    (6 * 64 * MB1)
#define OFF_KL    (7 * 64 * MB1)
#define OFF_VTH   (8 * 64 * MB1)
#define OFF_VTL   (9 * 64 * MB1)
#define OFF_WAH   (10 * 64 * MB1)
#define OFF_WAL   (11 * 64 * MB1)
#define OFF_NVTH  (12 * 64 * MB1)
#define OFF_NVTL  (13 * 64 * MB1)
#define OFF_SF32  (14 * 64 * MB1)                 // 128MB fp32 scores
#define OFF_W0    (16 * 64 * MB1)                 // 8 x 2MB weight hi/lo

// ---------------------------------------------------------------------------
// sm_80+-portable PTX helpers (NO tcgen05 — unavailable via compute_103 PTX)
// ---------------------------------------------------------------------------
__device__ __forceinline__ uint32_t smem_to_u32(const void* p) {
    uint32_t a;
    asm("{ .reg .u64 t; cvta.to.shared.u64 t, %1; cvt.u32.u64 %0, t; }" : "=r"(a) : "l"(p));
    return a;
}
__device__ __forceinline__ void cp16(uint32_t dst, const void* src) {
    asm volatile("cp.async.cg.shared.global [%0], [%1], 16;" :: "r"(dst), "l"(src) : "memory");
}
__device__ __forceinline__ void ldsm4(uint32_t* r, uint32_t addr) {
    asm volatile("ldmatrix.sync.aligned.m8n8.x4.shared.b16 {%0,%1,%2,%3}, [%4];"
        : "=r"(r[0]), "=r"(r[1]), "=r"(r[2]), "=r"(r[3]) : "r"(addr));
}
__device__ __forceinline__ void mma_bf16(float* c, const uint32_t* a, const uint32_t* b) {
    asm volatile(
        "mma.sync.aligned.m16n8k16.row.col.f32.bf16.bf16.f32 "
        "{%0,%1,%2,%3}, {%4,%5,%6,%7}, {%8,%9}, {%0,%1,%2,%3};"
        : "+f"(c[0]), "+f"(c[1]), "+f"(c[2]), "+f"(c[3])
        : "r"(a[0]), "r"(a[1]), "r"(a[2]), "r"(a[3]), "r"(b[0]), "r"(b[1]));
}

__device__ __forceinline__ void split_bf16(float v, __nv_bfloat16& h, __nv_bfloat16& l) {
    h = __float2bfloat16(v);
    l = __float2bfloat16(v - __bfloat162float(h));
}

enum { EPI_TANH = 0, EPI_TANH_T = 1, EPI_SCALE = 2, EPI_SPLIT_T = 3, EPI_BIASRES = 4 };

// GEMM tiling: CTA 128x256, 512 threads = 16 warps (4x4), warp tile 32x64,
// BK=32, 3-stage cp.async pipeline. 1 CTA/SM but 4 warps/SMSP.
constexpr int NTHREADS = 512;
constexpr int STAGES = 3;
constexpr int BK = 32;
constexpr int CHUNKS = NC / BK;                    // 32
constexpr int TPAD = 40;                           // padded row (bf16), 80B
constexpr int ATB = 128 * TPAD * 2;                // 10240 (A tile)
constexpr int BTB = 256 * TPAD * 2;                // 20480 (B tile)
constexpr int STAGE_BYTES = 2 * ATB + 2 * BTB;     // 61440
constexpr int SMEM_BYTES = STAGES * STAGE_BYTES;   // 184320

// ---------------------------------------------------------------------------
// Split-bf16 mma.sync GEMM:  D[m,n] = sum_k A[m,k]*B[n,k]  (both K-major)
// ---------------------------------------------------------------------------
template<int EPI, bool ABATCH>
__global__ __launch_bounds__(NTHREADS, 1) void gemm_mma(
    const __nv_bfloat16* __restrict__ Ah, const __nv_bfloat16* __restrict__ Al,
    const __nv_bfloat16* __restrict__ Bh, const __nv_bfloat16* __restrict__ Bl,
    const float* __restrict__ bias, const float* __restrict__ resid,
    float* __restrict__ Of, __nv_bfloat16* __restrict__ Oh, __nv_bfloat16* __restrict__ Ol,
    float alpha)
{
    extern __shared__ char smem[];
    const uint32_t sb = smem_to_u32(smem);
    const int tid = threadIdx.x, lane = tid & 31, wid = tid >> 5;
    const int warp_m = wid & 3, warp_n = wid >> 2;        // 4 x 4 warps
    const int bx = blockIdx.x, by = blockIdx.y, bz = blockIdx.z;
    const size_t bat = (size_t)bz * MAT;
    const int m0 = by * 128, n0 = bx * 256;

    const __nv_bfloat16* srcA_h = Ah + (ABATCH ? bat : 0);
    const __nv_bfloat16* srcA_l = Al + (ABATCH ? bat : 0);
    const __nv_bfloat16* srcB_h = Bh + bat;
    const __nv_bfloat16* srcB_l = Bl + bat;

    auto load_chunk = [&](int chunk, int stage) {
        const int k0 = chunk * BK;
        const uint32_t sbase = sb + stage * STAGE_BYTES;
        // A hi/lo: 128 rows x 32 k  (512 cp16 each = 1 per thread)
        {
            int r = tid >> 2, c8 = (tid & 3) * 8;
            uint32_t so = (uint32_t)(r * TPAD + c8) * 2;
            const size_t go = (size_t)(m0 + r) * 1024 + k0 + c8;
            cp16(sbase + so, srcA_h + go);
            cp16(sbase + ATB + so, srcA_l + go);
        }
        // B hi/lo: 256 rows x 32 k  (1024 cp16 each = 2 per thread)
        #pragma unroll
        for (int t = 0; t < 2; ++t) {
            int gi = tid + t * NTHREADS;            // 0..1023
            int r = gi >> 2, c8 = (gi & 3) * 8;
            uint32_t so = (uint32_t)(r * TPAD + c8) * 2;
            const size_t go = (size_t)(n0 + r) * 1024 + k0 + c8;
            cp16(sbase + 2 * ATB + so, srcB_h + go);
            cp16(sbase + 2 * ATB + BTB + so, srcB_l + go);
        }
    };

    // prologue: stages 0,1
    load_chunk(0, 0);
    asm volatile("cp.async.commit_group;" ::: "memory");
    load_chunk(1, 1);
    asm volatile("cp.async.commit_group;" ::: "memory");

    float acc[2][8][4];
    #pragma unroll
    for (int mi = 0; mi < 2; ++mi)
        #pragma unroll
        for (int ni = 0; ni < 8; ++ni)
            #pragma unroll
            for (int e = 0; e < 4; ++e) acc[mi][ni][e] = 0.f;

    for (int c = 0; c < CHUNKS; ++c) {
        asm volatile("cp.async.wait_group 1;" ::: "memory");   // chunk c arrived
        __syncthreads();

        const int nc = c + STAGES - 1;
        if (nc < CHUNKS) load_chunk(nc, nc % STAGES);
        asm volatile("cp.async.commit_group;" ::: "memory");

        const uint32_t sbase = sb + (c % STAGES) * STAGE_BYTES;
        const uint32_t aHb = sbase, aLb = sbase + ATB;
        const uint32_t bHb = sbase + 2 * ATB, bLb = sbase + 2 * ATB + BTB;

        #pragma unroll
        for (int s16 = 0; s16 < 2; ++s16) {
            const int koff = s16 * 16;
            uint32_t ah[2][4], al[2][4];
            #pragma unroll
            for (int mi = 0; mi < 2; ++mi) {
                uint32_t ro = (uint32_t)((warp_m * 32 + mi * 16 + (lane & 15)) * TPAD) * 2
                            + (uint32_t)(koff + ((lane >> 4) << 3)) * 2;
                ldsm4(ah[mi], aHb + ro);
                ldsm4(al[mi], aLb + ro);
            }
            #pragma unroll
            for (int nj = 0; nj < 4; ++nj) {
                uint32_t bh[4], bl[4];
                uint32_t ro = (uint32_t)((warp_n * 64 + nj * 16 + (lane & 7) + ((lane >> 4) << 3)) * TPAD) * 2
                            + (uint32_t)(koff + (((lane >> 3) & 1) << 3)) * 2;
                ldsm4(bh, bHb + ro);
                ldsm4(bl, bLb + ro);
                #pragma unroll
                for (int mi = 0; mi < 2; ++mi)
                    #pragma unroll
                    for (int half = 0; half < 2; ++half) {
                        const int ni = nj * 2 + half;
                        const uint32_t* bhp = &bh[half * 2];
                        const uint32_t* blp = &bl[half * 2];
                        mma_bf16(acc[mi][ni], ah[mi], bhp);
                        mma_bf16(acc[mi][ni], ah[mi], blp);
                        mma_bf16(acc[mi][ni], al[mi], bhp);
                    }
            }
        }
    }

    // ------------------------------ epilogue -------------------------------
    const int erow = m0 + warp_m * 32;
    const int ecol = n0 + warp_n * 64;
    const int rl = lane >> 2, cl = (lane & 3) * 2;

    #pragma unroll
    for (int mi = 0; mi < 2; ++mi) {
        const int r0e = erow + mi * 16 + rl;           // rows r0e, r0e+8
        float b0 = 0.f, b1 = 0.f;
        if (EPI == EPI_TANH || EPI == EPI_TANH_T || EPI == EPI_BIASRES) {
            b0 = bias[r0e]; b1 = bias[r0e + 8];
        }
        #pragma unroll
        for (int ni = 0; ni < 8; ++ni) {
            const int c0e = ecol + ni * 8 + cl;
            float* a = acc[mi][ni];

            if (EPI == EPI_TANH) {
                float v00 = tanhf(a[0] + b0), v01 = tanhf(a[1] + b0);
                float v10 = tanhf(a[2] + b1), v11 = tanhf(a[3] + b1);
                __nv_bfloat16 h0, l0, h1, l1;
                split_bf16(v00, h0, l0); split_bf16(v01, h1, l1);
                __nv_bfloat162 ph{h0, h1}, pl{l0, l1};
                *(__nv_bfloat162*)(Oh + bat + (size_t)r0e * 1024 + c0e) = ph;
                *(__nv_bfloat162*)(Ol + bat + (size_t)r0e * 1024 + c0e) = pl;
                split_bf16(v10, h0, l0); split_bf16(v11, h1, l1);
                __nv_bfloat162 ph2{h0, h1}, pl2{l0, l1};
                *(__nv_bfloat162*)(Oh + bat + (size_t)(r0e + 8) * 1024 + c0e) = ph2;
                *(__nv_bfloat162*)(Ol + bat + (size_t)(r0e + 8) * 1024 + c0e) = pl2;
            } else if (EPI == EPI_TANH_T || EPI == EPI_SPLIT_T) {
                float v[4] = { a[0], a[1], a[2], a[3] };
                if (EPI == EPI_TANH_T) {
                    v[0] = tanhf(v[0] + b0); v[1] = tanhf(v[1] + b0);
                    v[2] = tanhf(v[2] + b1); v[3] = tanhf(v[3] + b1);
                }
                const int rr[4] = { r0e, r0e, r0e + 8, r0e + 8 };
                const int cc[4] = { c0e, c0e + 1, c0e, c0e + 1 };
                #pragma unroll
                for (int e = 0; e < 4; ++e) {
                    __nv_bfloat16 hh, ll;
                    split_bf16(v[e], hh, ll);
                    const size_t idx = bat + (size_t)cc[e] * 1024 + rr[e];
                    Oh[idx] = hh; Ol[idx] = ll;
                }
            } else if (EPI == EPI_SCALE) {
                float2 o0{a[0] * alpha, a[1] * alpha};
                float2 o1{a[2] * alpha, a[3] * alpha};
                *(float2*)(Of + bat + (size_t)r0e * 1024 + c0e) = o0;
                *(float2*)(Of + bat + (size_t)(r0e + 8) * 1024 + c0e) = o1;
            } else {  // EPI_BIASRES
                float2 r0v = *(const float2*)(resid + bat + (size_t)r0e * 1024 + c0e);
                float2 r1v = *(const float2*)(resid + bat + (size_t)(r0e + 8) * 1024 + c0e);
                float2 o0{a[0] + b0 + r0v.x, a[1] + b0 + r0v.y};
                float2 o1{a[2] + b1 + r1v.x, a[3] + b1 + r1v.y};
                *(float2*)(Of + bat + (size_t)r0e * 1024 + c0e) = o0;
                *(float2*)(Of + bat + (size_t)(r0e + 8) * 1024 + c0e) = o1;
            }
        }
    }
}

// ---------------------------------------------------------------------------
// fp32 -> bf16 hi/lo elementwise (weights)
// ---------------------------------------------------------------------------
__global__ __launch_bounds__(256) void split_k(const float* __restrict__ in,
                                               __nv_bfloat16* __restrict__ oh,
                                               __nv_bfloat16* __restrict__ ol) {
    size_t i = (size_t)blockIdx.x * 256 + threadIdx.x;
    float v = in[i];
    __nv_bfloat16 h, l;
    split_bf16(v, h, l);
    oh[i] = h; ol[i] = l;
}

// ---------------------------------------------------------------------------
// fp32 [B][C,S] -> transposed bf16 hi/lo [B][S,C]
// ---------------------------------------------------------------------------
__global__ __launch_bounds__(256) void transpose_split_k(
    const float* __restrict__ in, __nv_bfloat16* __restrict__ oh, __nv_bfloat16* __restrict__ ol) {
    __shared__ float t[32][33];
    const int tx = threadIdx.x, ty = threadIdx.y;   // 32x8
    const int s0 = blockIdx.x * 32, c0 = blockIdx.y * 32;
    const size_t bat = (size_t)blockIdx.z * MAT;
    #pragma unroll
    for (int i = 0; i < 4; ++i)
        t[ty + 8 * i][tx] = in[bat + (size_t)(c0 + ty + 8 * i) * 1024 + s0 + tx];
    __syncthreads();
    #pragma unroll
    for (int i = 0; i < 4; ++i) {
        float v = t[tx][ty + 8 * i];
        __nv_bfloat16 h, l;
        split_bf16(v, h, l);
        const size_t idx = bat + (size_t)(s0 + ty + 8 * i) * 1024 + c0 + tx;
        oh[idx] = h; ol[idx] = l;
    }
}

// ---------------------------------------------------------------------------
// Row softmax fp32 -> bf16 hi/lo weights
// ---------------------------------------------------------------------------
__global__ __launch_bounds__(256) void softmax_split_k(
    const float* __restrict__ data, __nv_bfloat16* __restrict__ oh, __nv_bfloat16* __restrict__ ol) {
    __shared__ float red[8];
    __shared__ float bval;
    const size_t row = blockIdx.x;
    const float* p = data + row * (size_t)NC;
    const int tid = threadIdx.x, lane = tid & 31, wid = tid >> 5;

    float4 v = ((const float4*)p)[tid];
    float mx = fmaxf(fmaxf(v.x, v.y), fmaxf(v.z, v.w));
    #pragma unroll
    for (int o = 16; o > 0; o >>= 1) mx = fmaxf(mx, __shfl_xor_sync(0xffffffffu, mx, o));
    if (lane == 0) red[wid] = mx;
    __syncthreads();
    if (tid < 32) {
        float t = (tid < 8) ? red[tid] : -INFINITY;
        #pragma unroll
        for (int o = 4; o > 0; o >>= 1) t = fmaxf(t, __shfl_xor_sync(0xffffffffu, t, o));
        if (tid == 0) bval = t;
    }
    __syncthreads();
    mx = bval;
    v.x = expf(v.x - mx); v.y = expf(v.y - mx);
    v.z = expf(v.z - mx); v.w = expf(v.w - mx);
    float s = (v.x + v.y) + (v.z + v.w);
    #pragma unroll
    for (int o = 16; o > 0; o >>= 1) s += __shfl_xor_sync(0xffffffffu, s, o);
    __syncthreads();
    if (lane == 0) red[wid] = s;
    __syncthreads();
    if (tid < 32) {
        float t = (tid < 8) ? red[tid] : 0.f;
        #pragma unroll
        for (int o = 4; o > 0; o >>= 1) t += __shfl_xor_sync(0xffffffffu, t, o);
        if (tid == 0) bval = t;
    }
    __syncthreads();
    const float inv = 1.f / bval;
    float vv[4] = {v.x * inv, v.y * inv, v.z * inv, v.w * inv};
    const size_t base = row * (size_t)NC + 4 * tid;
    #pragma unroll
    for (int j = 0; j < 4; ++j) {
        __nv_bfloat16 h, l;
        split_bf16(vv[j], h, l);
        oh[base + j] = h; ol[base + j] = l;
    }
}

// ---------------------------------------------------------------------------
extern "C" void kernel_launch(void* const* d_in, const int* in_sizes, int n_in,
                              void* d_out, int out_size)
{
    const float* shape_map = (const float*)d_in[0];
    const float* img_map   = (const float*)d_in[1];
    const float* wq = (const float*)d_in[2];
    const float* bq = (const float*)d_in[3];
    const float* wk = (const float*)d_in[4];
    const float* bk = (const float*)d_in[5];
    const float* wv = (const float*)d_in[6];
    const float* bv = (const float*)d_in[7];
    const float* wc = (const float*)d_in[8];
    const float* bc = (const float*)d_in[9];
    float* out = (float*)d_out;

    unsigned char* buf;
    cudaGetSymbolAddress((void**)&buf, g_buf);
    __nv_bfloat16* XSH = (__nv_bfloat16*)(buf + OFF_XSH);
    __nv_bfloat16* XSL = (__nv_bfloat16*)(buf + OFF_XSL);
    __nv_bfloat16* XIH = (__nv_bfloat16*)(buf + OFF_XIH);
    __nv_bfloat16* XIL = (__nv_bfloat16*)(buf + OFF_XIL);
    __nv_bfloat16* QH  = (__nv_bfloat16*)(buf + OFF_QH);
    __nv_bfloat16* QL  = (__nv_bfloat16*)(buf + OFF_QL);
    __nv_bfloat16* KH  = (__nv_bfloat16*)(buf + OFF_KH);
    __nv_bfloat16* KL  = (__nv_bfloat16*)(buf + OFF_KL);
    __nv_bfloat16* VTH = (__nv_bfloat16*)(buf + OFF_VTH);
    __nv_bfloat16* VTL = (__nv_bfloat16*)(buf + OFF_VTL);
    __nv_bfloat16* WAH = (__nv_bfloat16*)(buf + OFF_WAH);
    __nv_bfloat16* WAL = (__nv_bfloat16*)(buf + OFF_WAL);
    __nv_bfloat16* NVTH = (__nv_bfloat16*)(buf + OFF_NVTH);
    __nv_bfloat16* NVTL = (__nv_bfloat16*)(buf + OFF_NVTL);
    float* SF = (float*)(buf + OFF_SF32);
    __nv_bfloat16* W[8];   // qh,ql,kh,kl,vh,vl,ch,cl
    for (int i = 0; i < 8; ++i) W[i] = (__nv_bfloat16*)(buf + OFF_W0 + (size_t)i * 2 * MB1);

    cudaFuncSetAttribute(gemm_mma<EPI_TANH, false>,   cudaFuncAttributeMaxDynamicSharedMemorySize, SMEM_BYTES);
    cudaFuncSetAttribute(gemm_mma<EPI_TANH_T, false>, cudaFuncAttributeMaxDynamicSharedMemorySize, SMEM_BYTES);
    cudaFuncSetAttribute(gemm_mma<EPI_SCALE, true>,   cudaFuncAttributeMaxDynamicSharedMemorySize, SMEM_BYTES);
    cudaFuncSetAttribute(gemm_mma<EPI_SPLIT_T, true>, cudaFuncAttributeMaxDynamicSharedMemorySize, SMEM_BYTES);
    cudaFuncSetAttribute(gemm_mma<EPI_BIASRES, false>,cudaFuncAttributeMaxDynamicSharedMemorySize, SMEM_BYTES);

    const dim3 grid(NS / 256, NC / 128, NB);   // (4, 8, 32)

    // 0..2: wq split, shape transpose, GEMM Q
    split_k<<<MAT / 256, 256>>>(wq, W[0], W[1]);
    transpose_split_k<<<dim3(32, 32, NB), dim3(32, 8)>>>(shape_map, XSH, XSL);
    gemm_mma<EPI_TANH, false><<<grid, NTHREADS, SMEM_BYTES>>>(W[0], W[1], XSH, XSL, bq, nullptr, nullptr, QH, QL, 0.f);
    // 3..5: wk split, img transpose, GEMM K
    split_k<<<MAT / 256, 256>>>(wk, W[2], W[3]);
    transpose_split_k<<<dim3(32, 32, NB), dim3(32, 8)>>>(img_map, XIH, XIL);
    gemm_mma<EPI_TANH, false><<<grid, NTHREADS, SMEM_BYTES>>>(W[2], W[3], XIH, XIL, bk, nullptr, nullptr, KH, KL, 0.f);
    // 6..7: wv split, GEMM V (stored transposed [S,C])
    split_k<<<MAT / 256, 256>>>(wv, W[4], W[5]);
    gemm_mma<EPI_TANH_T, false><<<grid, NTHREADS, SMEM_BYTES>>>(W[4], W[5], XIH, XIL, bv, nullptr, nullptr, VTH, VTL, 0.f);
    // 8: wc split
    split_k<<<MAT / 256, 256>>>(wc, W[6], W[7]);
    // 9: scores = (Q @ K^T) / 32 -> fp32
    gemm_mma<EPI_SCALE, true><<<grid, NTHREADS, SMEM_BYTES>>>(QH, QL, KH, KL, nullptr, nullptr, SF, nullptr, nullptr, 0.03125f);
    // 10: softmax rows -> bf16 hi/lo
    softmax_split_k<<<NB * NC, 256>>>(SF, WAH, WAL);
    // 11: new_v = weights @ V (stored transposed [S,C])
    gemm_mma<EPI_SPLIT_T, true><<<grid, NTHREADS, SMEM_BYTES>>>(WAH, WAL, VTH, VTL, nullptr, nullptr, nullptr, NVTH, NVTL, 0.f);
    // 12: out = Wc @ new_v + bc + shape_map
    gemm_mma<EPI_BIASRES, false><<<grid, NTHREADS, SMEM_BYTES>>>(W[6], W[7], NVTH, NVTL, bc, shape_map, out, nullptr, nullptr, 0.f);
}

// round 10
// speedup vs baseline: 2.1453x; 2.1177x over previous
#include <cuda_runtime.h>
#include <cuda_fp16.h>
#include <cstdint>
#include <math.h>

constexpr int NB = 32;
constexpr int NC = 1024;
constexpr int NS = 1024;
constexpr size_t MAT = (size_t)NC * NS;           // 1M elems
constexpr size_t MB1 = 1u << 20;

// ---------------------------------------------------------------------------
// One big scratch buffer (device global — allocation-guard safe)
// 7 fp16 batched tensors (64MB) + fp32 scores (128MB) + 4 fp16 weights (2MB)
// ---------------------------------------------------------------------------
__device__ __align__(128) unsigned char g_buf[600 * MB1];

#define OFF_XS    (0 * 64 * MB1)
#define OFF_XI    (1 * 64 * MB1)
#define OFF_Q     (2 * 64 * MB1)
#define OFF_K     (3 * 64 * MB1)
#define OFF_VT    (4 * 64 * MB1)
#define OFF_WA    (5 * 64 * MB1)
#define OFF_NVT   (6 * 64 * MB1)
#define OFF_SF32  (7 * 64 * MB1)                  // 128MB fp32 scores
#define OFF_W0    (9 * 64 * MB1)                  // 4 x 2MB fp16 weights

// ---------------------------------------------------------------------------
// sm_80+-portable PTX helpers (NO tcgen05 — unavailable via compute_103 PTX)
// ---------------------------------------------------------------------------
__device__ __forceinline__ uint32_t smem_to_u32(const void* p) {
    uint32_t a;
    asm("{ .reg .u64 t; cvta.to.shared.u64 t, %1; cvt.u32.u64 %0, t; }" : "=r"(a) : "l"(p));
    return a;
}
__device__ __forceinline__ void cp16(uint32_t dst, const void* src) {
    asm volatile("cp.async.cg.shared.global [%0], [%1], 16;" :: "r"(dst), "l"(src) : "memory");
}
__device__ __forceinline__ void ldsm4(uint32_t* r, uint32_t addr) {
    asm volatile("ldmatrix.sync.aligned.m8n8.x4.shared.b16 {%0,%1,%2,%3}, [%4];"
        : "=r"(r[0]), "=r"(r[1]), "=r"(r[2]), "=r"(r[3]) : "r"(addr));
}
__device__ __forceinline__ void mma_f16(float* c, const uint32_t* a, const uint32_t* b) {
    asm volatile(
        "mma.sync.aligned.m16n8k16.row.col.f32.f16.f16.f32 "
        "{%0,%1,%2,%3}, {%4,%5,%6,%7}, {%8,%9}, {%0,%1,%2,%3};"
        : "+f"(c[0]), "+f"(c[1]), "+f"(c[2]), "+f"(c[3])
        : "r"(a[0]), "r"(a[1]), "r"(a[2]), "r"(a[3]), "r"(b[0]), "r"(b[1]));
}

enum { EPI_TANH = 0, EPI_TANH_T = 1, EPI_SCALE = 2, EPI_CAST_T = 3, EPI_BIASRES = 4 };

// GEMM tiling: CTA 128x256, 512 threads = 16 warps (4x4), warp tile 32x64,
// BK=32, 3-stage cp.async pipeline.
constexpr int NTHREADS = 512;
constexpr int STAGES = 3;
constexpr int BK = 32;
constexpr int CHUNKS = NC / BK;                    // 32
constexpr int TPAD = 40;                           // padded row (fp16), 80B
constexpr int ATB = 128 * TPAD * 2;                // 10240 (A tile)
constexpr int BTB = 256 * TPAD * 2;                // 20480 (B tile)
constexpr int STAGE_BYTES = ATB + BTB;             // 30720
constexpr int SMEM_BYTES = STAGES * STAGE_BYTES;   // 92160

// ---------------------------------------------------------------------------
// fp16 mma.sync GEMM:  D[m,n] = sum_k A[m,k]*B[n,k]  (both K-major fp16)
// ---------------------------------------------------------------------------
template<int EPI, bool ABATCH>
__global__ __launch_bounds__(NTHREADS, 1) void gemm_mma(
    const __half* __restrict__ A, const __half* __restrict__ B,
    const float* __restrict__ bias, const float* __restrict__ resid,
    float* __restrict__ Of, __half* __restrict__ Oh,
    float alpha)
{
    extern __shared__ char smem[];
    const uint32_t sb = smem_to_u32(smem);
    const int tid = threadIdx.x, lane = tid & 31, wid = tid >> 5;
    const int warp_m = wid & 3, warp_n = wid >> 2;        // 4 x 4 warps
    const int bx = blockIdx.x, by = blockIdx.y, bz = blockIdx.z;
    const size_t bat = (size_t)bz * MAT;
    const int m0 = by * 128, n0 = bx * 256;

    const __half* srcA = A + (ABATCH ? bat : 0);
    const __half* srcB = B + bat;

    auto load_chunk = [&](int chunk, int stage) {
        const int k0 = chunk * BK;
        const uint32_t sbase = sb + stage * STAGE_BYTES;
        // A: 128 rows x 32 k = 512 cp16 (1 per thread)
        {
            int r = tid >> 2, c8 = (tid & 3) * 8;
            cp16(sbase + (uint32_t)(r * TPAD + c8) * 2,
                 srcA + (size_t)(m0 + r) * 1024 + k0 + c8);
        }
        // B: 256 rows x 32 k = 1024 cp16 (2 per thread)
        #pragma unroll
        for (int t = 0; t < 2; ++t) {
            int gi = tid + t * NTHREADS;            // 0..1023
            int r = gi >> 2, c8 = (gi & 3) * 8;
            cp16(sbase + ATB + (uint32_t)(r * TPAD + c8) * 2,
                 srcB + (size_t)(n0 + r) * 1024 + k0 + c8);
        }
    };

    // prologue: stages 0,1
    load_chunk(0, 0);
    asm volatile("cp.async.commit_group;" ::: "memory");
    load_chunk(1, 1);
    asm volatile("cp.async.commit_group;" ::: "memory");

    float acc[2][8][4];
    #pragma unroll
    for (int mi = 0; mi < 2; ++mi)
        #pragma unroll
        for (int ni = 0; ni < 8; ++ni)
            #pragma unroll
            for (int e = 0; e < 4; ++e) acc[mi][ni][e] = 0.f;

    for (int c = 0; c < CHUNKS; ++c) {
        asm volatile("cp.async.wait_group 1;" ::: "memory");   // chunk c arrived
        __syncthreads();

        const int nc = c + STAGES - 1;
        if (nc < CHUNKS) load_chunk(nc, nc % STAGES);
        asm volatile("cp.async.commit_group;" ::: "memory");

        const uint32_t sbase = sb + (c % STAGES) * STAGE_BYTES;
        const uint32_t aB = sbase, bB = sbase + ATB;

        #pragma unroll
        for (int s16 = 0; s16 < 2; ++s16) {
            const int koff = s16 * 16;
            uint32_t ah[2][4];
            #pragma unroll
            for (int mi = 0; mi < 2; ++mi) {
                uint32_t ro = (uint32_t)((warp_m * 32 + mi * 16 + (lane & 15)) * TPAD) * 2
                            + (uint32_t)(koff + ((lane >> 4) << 3)) * 2;
                ldsm4(ah[mi], aB + ro);
            }
            #pragma unroll
            for (int nj = 0; nj < 4; ++nj) {
                uint32_t bh[4];
                uint32_t ro = (uint32_t)((warp_n * 64 + nj * 16 + (lane & 7) + ((lane >> 4) << 3)) * TPAD) * 2
                            + (uint32_t)(koff + (((lane >> 3) & 1) << 3)) * 2;
                ldsm4(bh, bB + ro);
                #pragma unroll
                for (int mi = 0; mi < 2; ++mi)
                    #pragma unroll
                    for (int half = 0; half < 2; ++half)
                        mma_f16(acc[mi][nj * 2 + half], ah[mi], &bh[half * 2]);
            }
        }
    }

    // ------------------------------ epilogue -------------------------------
    const int erow = m0 + warp_m * 32;
    const int ecol = n0 + warp_n * 64;
    const int rl = lane >> 2, cl = (lane & 3) * 2;

    #pragma unroll
    for (int mi = 0; mi < 2; ++mi) {
        const int r0e = erow + mi * 16 + rl;           // rows r0e, r0e+8
        float b0 = 0.f, b1 = 0.f;
        if (EPI == EPI_TANH || EPI == EPI_TANH_T || EPI == EPI_BIASRES) {
            b0 = bias[r0e]; b1 = bias[r0e + 8];
        }
        #pragma unroll
        for (int ni = 0; ni < 8; ++ni) {
            const int c0e = ecol + ni * 8 + cl;
            float* a = acc[mi][ni];

            if (EPI == EPI_TANH) {
                float v00 = tanhf(a[0] + b0), v01 = tanhf(a[1] + b0);
                float v10 = tanhf(a[2] + b1), v11 = tanhf(a[3] + b1);
                *(__half2*)(Oh + bat + (size_t)r0e * 1024 + c0e) =
                    __floats2half2_rn(v00, v01);
                *(__half2*)(Oh + bat + (size_t)(r0e + 8) * 1024 + c0e) =
                    __floats2half2_rn(v10, v11);
            } else if (EPI == EPI_TANH_T || EPI == EPI_CAST_T) {
                float v[4] = { a[0], a[1], a[2], a[3] };
                if (EPI == EPI_TANH_T) {
                    v[0] = tanhf(v[0] + b0); v[1] = tanhf(v[1] + b0);
                    v[2] = tanhf(v[2] + b1); v[3] = tanhf(v[3] + b1);
                }
                const int rr[4] = { r0e, r0e, r0e + 8, r0e + 8 };
                const int cc[4] = { c0e, c0e + 1, c0e, c0e + 1 };
                #pragma unroll
                for (int e = 0; e < 4; ++e)
                    Oh[bat + (size_t)cc[e] * 1024 + rr[e]] = __float2half(v[e]);
            } else if (EPI == EPI_SCALE) {
                float2 o0{a[0] * alpha, a[1] * alpha};
                float2 o1{a[2] * alpha, a[3] * alpha};
                *(float2*)(Of + bat + (size_t)r0e * 1024 + c0e) = o0;
                *(float2*)(Of + bat + (size_t)(r0e + 8) * 1024 + c0e) = o1;
            } else {  // EPI_BIASRES
                float2 r0v = *(const float2*)(resid + bat + (size_t)r0e * 1024 + c0e);
                float2 r1v = *(const float2*)(resid + bat + (size_t)(r0e + 8) * 1024 + c0e);
                float2 o0{a[0] + b0 + r0v.x, a[1] + b0 + r0v.y};
                float2 o1{a[2] + b1 + r1v.x, a[3] + b1 + r1v.y};
                *(float2*)(Of + bat + (size_t)r0e * 1024 + c0e) = o0;
                *(float2*)(Of + bat + (size_t)(r0e + 8) * 1024 + c0e) = o1;
            }
        }
    }
}

// ---------------------------------------------------------------------------
// fp32 -> fp16 elementwise (weights)
// ---------------------------------------------------------------------------
__global__ __launch_bounds__(256) void cast_k(const float* __restrict__ in,
                                              __half* __restrict__ o) {
    size_t i = ((size_t)blockIdx.x * 256 + threadIdx.x) * 4;
    float4 v = *(const float4*)(in + i);
    __half2 a = __floats2half2_rn(v.x, v.y);
    __half2 b = __floats2half2_rn(v.z, v.w);
    *(__half2*)(o + i) = a;
    *(__half2*)(o + i + 2) = b;
}

// ---------------------------------------------------------------------------
// fp32 [B][C,S] -> transposed fp16 [B][S,C]
// ---------------------------------------------------------------------------
__global__ __launch_bounds__(256) void transpose_cast_k(
    const float* __restrict__ in, __half* __restrict__ o) {
    __shared__ float t[32][33];
    const int tx = threadIdx.x, ty = threadIdx.y;   // 32x8
    const int s0 = blockIdx.x * 32, c0 = blockIdx.y * 32;
    const size_t bat = (size_t)blockIdx.z * MAT;
    #pragma unroll
    for (int i = 0; i < 4; ++i)
        t[ty + 8 * i][tx] = in[bat + (size_t)(c0 + ty + 8 * i) * 1024 + s0 + tx];
    __syncthreads();
    #pragma unroll
    for (int i = 0; i < 4; ++i)
        o[bat + (size_t)(s0 + ty + 8 * i) * 1024 + c0 + tx] = __float2half(t[tx][ty + 8 * i]);
}

// ---------------------------------------------------------------------------
// Row softmax fp32 -> fp16 weights
// ---------------------------------------------------------------------------
__global__ __launch_bounds__(256) void softmax_cast_k(
    const float* __restrict__ data, __half* __restrict__ o) {
    __shared__ float red[8];
    __shared__ float bval;
    const size_t row = blockIdx.x;
    const float* p = data + row * (size_t)NC;
    const int tid = threadIdx.x, lane = tid & 31, wid = tid >> 5;

    float4 v = ((const float4*)p)[tid];
    float mx = fmaxf(fmaxf(v.x, v.y), fmaxf(v.z, v.w));
    #pragma unroll
    for (int off = 16; off > 0; off >>= 1) mx = fmaxf(mx, __shfl_xor_sync(0xffffffffu, mx, off));
    if (lane == 0) red[wid] = mx;
    __syncthreads();
    if (tid < 32) {
        float t = (tid < 8) ? red[tid] : -INFINITY;
        #pragma unroll
        for (int off = 4; off > 0; off >>= 1) t = fmaxf(t, __shfl_xor_sync(0xffffffffu, t, off));
        if (tid == 0) bval = t;
    }
    __syncthreads();
    mx = bval;
    v.x = expf(v.x - mx); v.y = expf(v.y - mx);
    v.z = expf(v.z - mx); v.w = expf(v.w - mx);
    float s = (v.x + v.y) + (v.z + v.w);
    #pragma unroll
    for (int off = 16; off > 0; off >>= 1) s += __shfl_xor_sync(0xffffffffu, s, off);
    __syncthreads();
    if (lane == 0) red[wid] = s;
    __syncthreads();
    if (tid < 32) {
        float t = (tid < 8) ? red[tid] : 0.f;
        #pragma unroll
        for (int off = 4; off > 0; off >>= 1) t += __shfl_xor_sync(0xffffffffu, t, off);
        if (tid == 0) bval = t;
    }
    __syncthreads();
    const float inv = 1.f / bval;
    const size_t base = row * (size_t)NC + 4 * tid;
    *(__half2*)(o + base)     = __floats2half2_rn(v.x * inv, v.y * inv);
    *(__half2*)(o + base + 2) = __floats2half2_rn(v.z * inv, v.w * inv);
}

// ---------------------------------------------------------------------------
extern "C" void kernel_launch(void* const* d_in, const int* in_sizes, int n_in,
                              void* d_out, int out_size)
{
    const float* shape_map = (const float*)d_in[0];
    const float* img_map   = (const float*)d_in[1];
    const float* wq = (const float*)d_in[2];
    const float* bq = (const float*)d_in[3];
    const float* wk = (const float*)d_in[4];
    const float* bk = (const float*)d_in[5];
    const float* wv = (const float*)d_in[6];
    const float* bv = (const float*)d_in[7];
    const float* wc = (const float*)d_in[8];
    const float* bc = (const float*)d_in[9];
    float* out = (float*)d_out;

    unsigned char* buf;
    cudaGetSymbolAddress((void**)&buf, g_buf);
    __half* XS  = (__half*)(buf + OFF_XS);
    __half* XI  = (__half*)(buf + OFF_XI);
    __half* Q   = (__half*)(buf + OFF_Q);
    __half* K   = (__half*)(buf + OFF_K);
    __half* VT  = (__half*)(buf + OFF_VT);
    __half* WA  = (__half*)(buf + OFF_WA);
    __half* NVT = (__half*)(buf + OFF_NVT);
    float*  SF  = (float*)(buf + OFF_SF32);
    __half* W[4];   // q,k,v,c
    for (int i = 0; i < 4; ++i) W[i] = (__half*)(buf + OFF_W0 + (size_t)i * 2 * MB1);

    cudaFuncSetAttribute(gemm_mma<EPI_TANH, false>,   cudaFuncAttributeMaxDynamicSharedMemorySize, SMEM_BYTES);
    cudaFuncSetAttribute(gemm_mma<EPI_TANH_T, false>, cudaFuncAttributeMaxDynamicSharedMemorySize, SMEM_BYTES);
    cudaFuncSetAttribute(gemm_mma<EPI_SCALE, true>,   cudaFuncAttributeMaxDynamicSharedMemorySize, SMEM_BYTES);
    cudaFuncSetAttribute(gemm_mma<EPI_CAST_T, true>,  cudaFuncAttributeMaxDynamicSharedMemorySize, SMEM_BYTES);
    cudaFuncSetAttribute(gemm_mma<EPI_BIASRES, false>,cudaFuncAttributeMaxDynamicSharedMemorySize, SMEM_BYTES);

    const dim3 grid(NS / 256, NC / 128, NB);   // (4, 8, 32)

    // converts
    cast_k<<<MAT / 1024, 256>>>(wq, W[0]);
    cast_k<<<MAT / 1024, 256>>>(wk, W[1]);
    cast_k<<<MAT / 1024, 256>>>(wv, W[2]);
    cast_k<<<MAT / 1024, 256>>>(wc, W[3]);
    transpose_cast_k<<<dim3(32, 32, NB), dim3(32, 8)>>>(shape_map, XS);
    transpose_cast_k<<<dim3(32, 32, NB), dim3(32, 8)>>>(img_map, XI);

    // Q = tanh(Wq@Xs + bq) [C,S]; K likewise; V stored transposed [S,C]
    gemm_mma<EPI_TANH, false><<<grid, NTHREADS, SMEM_BYTES>>>(W[0], XS, bq, nullptr, nullptr, Q, 0.f);
    gemm_mma<EPI_TANH, false><<<grid, NTHREADS, SMEM_BYTES>>>(W[1], XI, bk, nullptr, nullptr, K, 0.f);
    gemm_mma<EPI_TANH_T, false><<<grid, NTHREADS, SMEM_BYTES>>>(W[2], XI, bv, nullptr, nullptr, VT, 0.f);
    // scores = (Q @ K^T) / 32 -> fp32
    gemm_mma<EPI_SCALE, true><<<grid, NTHREADS, SMEM_BYTES>>>(Q, K, nullptr, nullptr, SF, nullptr, 0.03125f);
    // softmax rows -> fp16 weights
    softmax_cast_k<<<NB * NC, 256>>>(SF, WA);
    // new_v = weights @ V (stored transposed [S,C])
    gemm_mma<EPI_CAST_T, true><<<grid, NTHREADS, SMEM_BYTES>>>(WA, VT, nullptr, nullptr, nullptr, NVT, 0.f);
    // out = Wc @ new_v + bc + shape_map
    gemm_mma<EPI_BIASRES, false><<<grid, NTHREADS, SMEM_BYTES>>>(W[3], NVT, bc, shape_map, out, nullptr, 0.f);
}

// round 11
// speedup vs baseline: 2.1614x; 1.0075x over previous
#include <cuda_runtime.h>
#include <cuda_fp16.h>
#include <cstdint>
#include <math.h>

constexpr int NB = 32;
constexpr int NC = 1024;
constexpr int NS = 1024;
constexpr size_t MAT = (size_t)NC * NS;           // 1M elems
constexpr size_t MB1 = 1u << 20;

// ---------------------------------------------------------------------------
// One big scratch buffer (device global — allocation-guard safe)
// ---------------------------------------------------------------------------
__device__ __align__(128) unsigned char g_buf[600 * MB1];

#define OFF_XS    (0 * 64 * MB1)
#define OFF_XI    (1 * 64 * MB1)
#define OFF_Q     (2 * 64 * MB1)
#define OFF_K     (3 * 64 * MB1)
#define OFF_VT    (4 * 64 * MB1)
#define OFF_WA    (5 * 64 * MB1)
#define OFF_NVT   (6 * 64 * MB1)
#define OFF_SF32  (7 * 64 * MB1)                  // 128MB fp32 scores
#define OFF_W0    (9 * 64 * MB1)                  // 4 x 2MB fp16 weights

// ---------------------------------------------------------------------------
// sm_80+-portable PTX helpers (NO tcgen05 — unavailable via compute_103 PTX)
// ---------------------------------------------------------------------------
__device__ __forceinline__ uint32_t smem_to_u32(const void* p) {
    uint32_t a;
    asm("{ .reg .u64 t; cvta.to.shared.u64 t, %1; cvt.u32.u64 %0, t; }" : "=r"(a) : "l"(p));
    return a;
}
__device__ __forceinline__ void cp16(uint32_t dst, const void* src) {
    asm volatile("cp.async.cg.shared.global [%0], [%1], 16;" :: "r"(dst), "l"(src) : "memory");
}
__device__ __forceinline__ void ldsm4(uint32_t* r, uint32_t addr) {
    asm volatile("ldmatrix.sync.aligned.m8n8.x4.shared.b16 {%0,%1,%2,%3}, [%4];"
        : "=r"(r[0]), "=r"(r[1]), "=r"(r[2]), "=r"(r[3]) : "r"(addr));
}
__device__ __forceinline__ void mma_f16(float* c, const uint32_t* a, const uint32_t* b) {
    asm volatile(
        "mma.sync.aligned.m16n8k16.row.col.f32.f16.f16.f32 "
        "{%0,%1,%2,%3}, {%4,%5,%6,%7}, {%8,%9}, {%0,%1,%2,%3};"
        : "+f"(c[0]), "+f"(c[1]), "+f"(c[2]), "+f"(c[3])
        : "r"(a[0]), "r"(a[1]), "r"(a[2]), "r"(a[3]), "r"(b[0]), "r"(b[1]));
}

enum { EPI_TANH = 0,      // row bias + tanh, fp16 out
       EPI_TANH_CB = 1,   // column bias + tanh, fp16 out
       EPI_SCALE = 2,     // * alpha, fp32 out
       EPI_CAST = 3,      // plain fp16 out
       EPI_BIASRES = 4 }; // row bias + residual, fp32 out

// GEMM tiling: CTA 128x256, 512 threads = 16 warps (4x4), warp tile 32x64,
// BK=32, 3-stage cp.async pipeline.
constexpr int NTHREADS = 512;
constexpr int STAGES = 3;
constexpr int BK = 32;
constexpr int CHUNKS = NC / BK;                    // 32
constexpr int TPAD = 40;                           // padded row (fp16), 80B
constexpr int ATB = 128 * TPAD * 2;                // 10240 (A tile)
constexpr int BTB = 256 * TPAD * 2;                // 20480 (B tile)
constexpr int STAGE_BYTES = ATB + BTB;             // 30720
constexpr int SMEM_BYTES = STAGES * STAGE_BYTES;   // 92160

// ---------------------------------------------------------------------------
// fp16 mma.sync GEMM:  D[m,n] = sum_k A[m,k]*B[n,k]  (both K-major fp16)
// All epilogues store coalesced row-major output.
// ---------------------------------------------------------------------------
template<int EPI, bool ABATCH, bool BBATCH>
__global__ __launch_bounds__(NTHREADS, 1) void gemm_mma(
    const __half* __restrict__ A, const __half* __restrict__ B,
    const float* __restrict__ bias, const float* __restrict__ resid,
    float* __restrict__ Of, __half* __restrict__ Oh,
    float alpha)
{
    extern __shared__ char smem[];
    const uint32_t sb = smem_to_u32(smem);
    const int tid = threadIdx.x, lane = tid & 31, wid = tid >> 5;
    const int warp_m = wid & 3, warp_n = wid >> 2;        // 4 x 4 warps
    const int bx = blockIdx.x, by = blockIdx.y, bz = blockIdx.z;
    const size_t bat = (size_t)bz * MAT;
    const int m0 = by * 128, n0 = bx * 256;

    const __half* srcA = A + (ABATCH ? bat : 0);
    const __half* srcB = B + (BBATCH ? bat : 0);

    auto load_chunk = [&](int chunk, int stage) {
        const int k0 = chunk * BK;
        const uint32_t sbase = sb + stage * STAGE_BYTES;
        // A: 128 rows x 32 k = 512 cp16 (1 per thread)
        {
            int r = tid >> 2, c8 = (tid & 3) * 8;
            cp16(sbase + (uint32_t)(r * TPAD + c8) * 2,
                 srcA + (size_t)(m0 + r) * 1024 + k0 + c8);
        }
        // B: 256 rows x 32 k = 1024 cp16 (2 per thread)
        #pragma unroll
        for (int t = 0; t < 2; ++t) {
            int gi = tid + t * NTHREADS;            // 0..1023
            int r = gi >> 2, c8 = (gi & 3) * 8;
            cp16(sbase + ATB + (uint32_t)(r * TPAD + c8) * 2,
                 srcB + (size_t)(n0 + r) * 1024 + k0 + c8);
        }
    };

    // prologue: stages 0,1
    load_chunk(0, 0);
    asm volatile("cp.async.commit_group;" ::: "memory");
    load_chunk(1, 1);
    asm volatile("cp.async.commit_group;" ::: "memory");

    float acc[2][8][4];
    #pragma unroll
    for (int mi = 0; mi < 2; ++mi)
        #pragma unroll
        for (int ni = 0; ni < 8; ++ni)
            #pragma unroll
            for (int e = 0; e < 4; ++e) acc[mi][ni][e] = 0.f;

    for (int c = 0; c < CHUNKS; ++c) {
        asm volatile("cp.async.wait_group 1;" ::: "memory");   // chunk c arrived
        __syncthreads();

        const int nc = c + STAGES - 1;
        if (nc < CHUNKS) load_chunk(nc, nc % STAGES);
        asm volatile("cp.async.commit_group;" ::: "memory");

        const uint32_t sbase = sb + (c % STAGES) * STAGE_BYTES;
        const uint32_t aB = sbase, bB = sbase + ATB;

        #pragma unroll
        for (int s16 = 0; s16 < 2; ++s16) {
            const int koff = s16 * 16;
            uint32_t ah[2][4];
            #pragma unroll
            for (int mi = 0; mi < 2; ++mi) {
                uint32_t ro = (uint32_t)((warp_m * 32 + mi * 16 + (lane & 15)) * TPAD) * 2
                            + (uint32_t)(koff + ((lane >> 4) << 3)) * 2;
                ldsm4(ah[mi], aB + ro);
            }
            #pragma unroll
            for (int nj = 0; nj < 4; ++nj) {
                uint32_t bh[4];
                uint32_t ro = (uint32_t)((warp_n * 64 + nj * 16 + (lane & 7) + ((lane >> 4) << 3)) * TPAD) * 2
                            + (uint32_t)(koff + (((lane >> 3) & 1) << 3)) * 2;
                ldsm4(bh, bB + ro);
                #pragma unroll
                for (int mi = 0; mi < 2; ++mi)
                    #pragma unroll
                    for (int half = 0; half < 2; ++half)
                        mma_f16(acc[mi][nj * 2 + half], ah[mi], &bh[half * 2]);
            }
        }
    }

    // ------------------------------ epilogue (all coalesced) ----------------
    const int erow = m0 + warp_m * 32;
    const int ecol = n0 + warp_n * 64;
    const int rl = lane >> 2, cl = (lane & 3) * 2;

    #pragma unroll
    for (int mi = 0; mi < 2; ++mi) {
        const int r0e = erow + mi * 16 + rl;           // rows r0e, r0e+8
        float b0 = 0.f, b1 = 0.f;
        if (EPI == EPI_TANH || EPI == EPI_BIASRES) {
            b0 = bias[r0e]; b1 = bias[r0e + 8];
        }
        #pragma unroll
        for (int ni = 0; ni < 8; ++ni) {
            const int c0e = ecol + ni * 8 + cl;
            float* a = acc[mi][ni];
            const size_t row0 = bat + (size_t)r0e * 1024 + c0e;
            const size_t row1 = bat + (size_t)(r0e + 8) * 1024 + c0e;

            if (EPI == EPI_TANH) {
                *(__half2*)(Oh + row0) = __floats2half2_rn(tanhf(a[0] + b0), tanhf(a[1] + b0));
                *(__half2*)(Oh + row1) = __floats2half2_rn(tanhf(a[2] + b1), tanhf(a[3] + b1));
            } else if (EPI == EPI_TANH_CB) {
                const float bc0 = bias[c0e], bc1 = bias[c0e + 1];
                *(__half2*)(Oh + row0) = __floats2half2_rn(tanhf(a[0] + bc0), tanhf(a[1] + bc1));
                *(__half2*)(Oh + row1) = __floats2half2_rn(tanhf(a[2] + bc0), tanhf(a[3] + bc1));
            } else if (EPI == EPI_CAST) {
                *(__half2*)(Oh + row0) = __floats2half2_rn(a[0], a[1]);
                *(__half2*)(Oh + row1) = __floats2half2_rn(a[2], a[3]);
            } else if (EPI == EPI_SCALE) {
                float2 o0{a[0] * alpha, a[1] * alpha};
                float2 o1{a[2] * alpha, a[3] * alpha};
                *(float2*)(Of + row0) = o0;
                *(float2*)(Of + row1) = o1;
            } else {  // EPI_BIASRES
                float2 r0v = *(const float2*)(resid + row0);
                float2 r1v = *(const float2*)(resid + row1);
                float2 o0{a[0] + b0 + r0v.x, a[1] + b0 + r0v.y};
                float2 o1{a[2] + b1 + r1v.x, a[3] + b1 + r1v.y};
                *(float2*)(Of + row0) = o0;
                *(float2*)(Of + row1) = o1;
            }
        }
    }
}

// ---------------------------------------------------------------------------
// fp32 -> fp16 elementwise (weights)
// ---------------------------------------------------------------------------
__global__ __launch_bounds__(256) void cast_k(const float* __restrict__ in,
                                              __half* __restrict__ o) {
    size_t i = ((size_t)blockIdx.x * 256 + threadIdx.x) * 4;
    float4 v = *(const float4*)(in + i);
    *(__half2*)(o + i)     = __floats2half2_rn(v.x, v.y);
    *(__half2*)(o + i + 2) = __floats2half2_rn(v.z, v.w);
}

// ---------------------------------------------------------------------------
// fp32 [B][C,S] -> transposed fp16 [B][S,C]
// ---------------------------------------------------------------------------
__global__ __launch_bounds__(256) void transpose_cast_k(
    const float* __restrict__ in, __half* __restrict__ o) {
    __shared__ float t[32][33];
    const int tx = threadIdx.x, ty = threadIdx.y;   // 32x8
    const int s0 = blockIdx.x * 32, c0 = blockIdx.y * 32;
    const size_t bat = (size_t)blockIdx.z * MAT;
    #pragma unroll
    for (int i = 0; i < 4; ++i)
        t[ty + 8 * i][tx] = in[bat + (size_t)(c0 + ty + 8 * i) * 1024 + s0 + tx];
    __syncthreads();
    #pragma unroll
    for (int i = 0; i < 4; ++i)
        o[bat + (size_t)(s0 + ty + 8 * i) * 1024 + c0 + tx] = __float2half(t[tx][ty + 8 * i]);
}

// ---------------------------------------------------------------------------
// Row softmax fp32 -> fp16 weights
// ---------------------------------------------------------------------------
__global__ __launch_bounds__(256) void softmax_cast_k(
    const float* __restrict__ data, __half* __restrict__ o) {
    __shared__ float red[8];
    __shared__ float bval;
    const size_t row = blockIdx.x;
    const float* p = data + row * (size_t)NC;
    const int tid = threadIdx.x, lane = tid & 31, wid = tid >> 5;

    float4 v = ((const float4*)p)[tid];
    float mx = fmaxf(fmaxf(v.x, v.y), fmaxf(v.z, v.w));
    #pragma unroll
    for (int off = 16; off > 0; off >>= 1) mx = fmaxf(mx, __shfl_xor_sync(0xffffffffu, mx, off));
    if (lane == 0) red[wid] = mx;
    __syncthreads();
    if (tid < 32) {
        float t = (tid < 8) ? red[tid] : -INFINITY;
        #pragma unroll
        for (int off = 4; off > 0; off >>= 1) t = fmaxf(t, __shfl_xor_sync(0xffffffffu, t, off));
        if (tid == 0) bval = t;
    }
    __syncthreads();
    mx = bval;
    v.x = expf(v.x - mx); v.y = expf(v.y - mx);
    v.z = expf(v.z - mx); v.w = expf(v.w - mx);
    float s = (v.x + v.y) + (v.z + v.w);
    #pragma unroll
    for (int off = 16; off > 0; off >>= 1) s += __shfl_xor_sync(0xffffffffu, s, off);
    __syncthreads();
    if (lane == 0) red[wid] = s;
    __syncthreads();
    if (tid < 32) {
        float t = (tid < 8) ? red[tid] : 0.f;
        #pragma unroll
        for (int off = 4; off > 0; off >>= 1) t += __shfl_xor_sync(0xffffffffu, t, off);
        if (tid == 0) bval = t;
    }
    __syncthreads();
    const float inv = 1.f / bval;
    const size_t base = row * (size_t)NC + 4 * tid;
    *(__half2*)(o + base)     = __floats2half2_rn(v.x * inv, v.y * inv);
    *(__half2*)(o + base + 2) = __floats2half2_rn(v.z * inv, v.w * inv);
}

// ---------------------------------------------------------------------------
extern "C" void kernel_launch(void* const* d_in, const int* in_sizes, int n_in,
                              void* d_out, int out_size)
{
    const float* shape_map = (const float*)d_in[0];
    const float* img_map   = (const float*)d_in[1];
    const float* wq = (const float*)d_in[2];
    const float* bq = (const float*)d_in[3];
    const float* wk = (const float*)d_in[4];
    const float* bk = (const float*)d_in[5];
    const float* wv = (const float*)d_in[6];
    const float* bv = (const float*)d_in[7];
    const float* wc = (const float*)d_in[8];
    const float* bc = (const float*)d_in[9];
    float* out = (float*)d_out;

    unsigned char* buf;
    cudaGetSymbolAddress((void**)&buf, g_buf);
    __half* XS  = (__half*)(buf + OFF_XS);
    __half* XI  = (__half*)(buf + OFF_XI);
    __half* Q   = (__half*)(buf + OFF_Q);
    __half* K   = (__half*)(buf + OFF_K);
    __half* VT  = (__half*)(buf + OFF_VT);
    __half* WA  = (__half*)(buf + OFF_WA);
    __half* NVT = (__half*)(buf + OFF_NVT);
    float*  SF  = (float*)(buf + OFF_SF32);
    __half* W[4];   // q,k,v,c
    for (int i = 0; i < 4; ++i) W[i] = (__half*)(buf + OFF_W0 + (size_t)i * 2 * MB1);

    cudaFuncSetAttribute(gemm_mma<EPI_TANH, false, true>,    cudaFuncAttributeMaxDynamicSharedMemorySize, SMEM_BYTES);
    cudaFuncSetAttribute(gemm_mma<EPI_TANH_CB, true, false>, cudaFuncAttributeMaxDynamicSharedMemorySize, SMEM_BYTES);
    cudaFuncSetAttribute(gemm_mma<EPI_SCALE, true, true>,    cudaFuncAttributeMaxDynamicSharedMemorySize, SMEM_BYTES);
    cudaFuncSetAttribute(gemm_mma<EPI_CAST, true, true>,     cudaFuncAttributeMaxDynamicSharedMemorySize, SMEM_BYTES);
    cudaFuncSetAttribute(gemm_mma<EPI_BIASRES, false, true>, cudaFuncAttributeMaxDynamicSharedMemorySize, SMEM_BYTES);

    const dim3 grid(4, 8, NB);   // n-tiles(256) x m-tiles(128) x batch

    // converts
    cast_k<<<MAT / 1024, 256>>>(wq, W[0]);
    cast_k<<<MAT / 1024, 256>>>(wk, W[1]);
    cast_k<<<MAT / 1024, 256>>>(wv, W[2]);
    cast_k<<<MAT / 1024, 256>>>(wc, W[3]);
    transpose_cast_k<<<dim3(32, 32, NB), dim3(32, 8)>>>(shape_map, XS);
    transpose_cast_k<<<dim3(32, 32, NB), dim3(32, 8)>>>(img_map, XI);

    // Q[c,s] = tanh(Wq@Xs + bq):  A=Wq [C,C], B=XS [S,C] batched -> [C,S]
    gemm_mma<EPI_TANH, false, true><<<grid, NTHREADS, SMEM_BYTES>>>(W[0], XS, bq, nullptr, nullptr, Q, 0.f);
    gemm_mma<EPI_TANH, false, true><<<grid, NTHREADS, SMEM_BYTES>>>(W[1], XI, bk, nullptr, nullptr, K, 0.f);
    // VT[s,c] = tanh(sum_d XI[s,d]*Wv[c,d] + bv[c]):  A=XI batched, B=Wv -> [S,C] coalesced
    gemm_mma<EPI_TANH_CB, true, false><<<grid, NTHREADS, SMEM_BYTES>>>(XI, W[2], bv, nullptr, nullptr, VT, 0.f);
    // scores[c,d] = (Q @ K^T)/32 -> fp32 [C,C]
    gemm_mma<EPI_SCALE, true, true><<<grid, NTHREADS, SMEM_BYTES>>>(Q, K, nullptr, nullptr, SF, nullptr, 0.03125f);
    // softmax rows -> fp16 weights
    softmax_cast_k<<<NB * NC, 256>>>(SF, WA);
    // NVT[s,c] = sum_d VT[s,d]*WA[c,d] = new_v^T -> [S,C] coalesced
    gemm_mma<EPI_CAST, true, true><<<grid, NTHREADS, SMEM_BYTES>>>(VT, WA, nullptr, nullptr, nullptr, NVT, 0.f);
    // out[c,s] = sum_d Wc[c,d]*NVT[s,d] + bc[c] + shape_map  -> fp32 [C,S]
    gemm_mma<EPI_BIASRES, false, true><<<grid, NTHREADS, SMEM_BYTES>>>(W[3], NVT, bc, shape_map, out, nullptr, 0.f);
}

// round 12
// speedup vs baseline: 2.5950x; 1.2006x over previous
#include <cuda_runtime.h>
#include <cuda_fp16.h>
#include <cstdint>
#include <math.h>

constexpr int NB = 32;
constexpr int NC = 1024;
constexpr int NS = 1024;
constexpr size_t MAT = (size_t)NC * NS;           // 1M elems
constexpr size_t MB1 = 1u << 20;

// ---------------------------------------------------------------------------
// One big scratch buffer (device global — allocation-guard safe)
// ---------------------------------------------------------------------------
__device__ __align__(128) unsigned char g_buf[600 * MB1];

#define OFF_XS    (0 * 64 * MB1)
#define OFF_XI    (1 * 64 * MB1)
#define OFF_Q     (2 * 64 * MB1)
#define OFF_K     (3 * 64 * MB1)
#define OFF_VT    (4 * 64 * MB1)
#define OFF_WA    (5 * 64 * MB1)
#define OFF_NVT   (6 * 64 * MB1)
#define OFF_SF32  (7 * 64 * MB1)                  // 128MB fp32 scores
#define OFF_W0    (9 * 64 * MB1)                  // 4 x 2MB fp16 weights

// ---------------------------------------------------------------------------
// sm_80+-portable PTX helpers (NO tcgen05 — unavailable via compute_103 PTX)
// ---------------------------------------------------------------------------
__device__ __forceinline__ uint32_t smem_to_u32(const void* p) {
    uint32_t a;
    asm("{ .reg .u64 t; cvta.to.shared.u64 t, %1; cvt.u32.u64 %0, t; }" : "=r"(a) : "l"(p));
    return a;
}
__device__ __forceinline__ void cp16(uint32_t dst, const void* src) {
    asm volatile("cp.async.cg.shared.global [%0], [%1], 16;" :: "r"(dst), "l"(src) : "memory");
}
__device__ __forceinline__ void ldsm4(uint32_t* r, uint32_t addr) {
    asm volatile("ldmatrix.sync.aligned.m8n8.x4.shared.b16 {%0,%1,%2,%3}, [%4];"
        : "=r"(r[0]), "=r"(r[1]), "=r"(r[2]), "=r"(r[3]) : "r"(addr));
}
__device__ __forceinline__ void mma_f16(float* c, const uint32_t* a, const uint32_t* b) {
    asm volatile(
        "mma.sync.aligned.m16n8k16.row.col.f32.f16.f16.f32 "
        "{%0,%1,%2,%3}, {%4,%5,%6,%7}, {%8,%9}, {%0,%1,%2,%3};"
        : "+f"(c[0]), "+f"(c[1]), "+f"(c[2]), "+f"(c[3])
        : "r"(a[0]), "r"(a[1]), "r"(a[2]), "r"(a[3]), "r"(b[0]), "r"(b[1]));
}

enum { EPI_TANH = 0,      // row bias + tanh, fp16 out
       EPI_TANH_CB = 1,   // column bias + tanh, fp16 out
       EPI_SCALE = 2,     // * alpha, fp32 out
       EPI_CAST = 3,      // plain fp16 out
       EPI_BIASRES = 4 }; // row bias + residual, fp32 out

// GEMM tiling: CTA 128x256, 512 threads = 16 warps (4x4), warp tile 32x64,
// BK=64, 3-stage cp.async pipeline (R6 precedent: halved barrier count -12%).
constexpr int NTHREADS = 512;
constexpr int STAGES = 3;
constexpr int BK = 64;
constexpr int CHUNKS = NC / BK;                    // 16
constexpr int TPAD = 72;                           // padded row (fp16), 144B
constexpr int ATB = 128 * TPAD * 2;                // 18432 (A tile)
constexpr int BTB = 256 * TPAD * 2;                // 36864 (B tile)
constexpr int STAGE_BYTES = ATB + BTB;             // 55296
constexpr int SMEM_BYTES = STAGES * STAGE_BYTES;   // 165888

// ---------------------------------------------------------------------------
// fp16 mma.sync GEMM:  D[m,n] = sum_k A[m,k]*B[n,k]  (both K-major fp16)
// All epilogues store coalesced row-major output.
// ---------------------------------------------------------------------------
template<int EPI, bool ABATCH, bool BBATCH>
__global__ __launch_bounds__(NTHREADS, 1) void gemm_mma(
    const __half* __restrict__ A, const __half* __restrict__ B,
    const float* __restrict__ bias, const float* __restrict__ resid,
    float* __restrict__ Of, __half* __restrict__ Oh,
    float alpha)
{
    extern __shared__ char smem[];
    const uint32_t sb = smem_to_u32(smem);
    const int tid = threadIdx.x, lane = tid & 31, wid = tid >> 5;
    const int warp_m = wid & 3, warp_n = wid >> 2;        // 4 x 4 warps
    const int bx = blockIdx.x, by = blockIdx.y, bz = blockIdx.z;
    const size_t bat = (size_t)bz * MAT;
    const int m0 = by * 128, n0 = bx * 256;

    const __half* srcA = A + (ABATCH ? bat : 0);
    const __half* srcB = B + (BBATCH ? bat : 0);

    auto load_chunk = [&](int chunk, int stage) {
        const int k0 = chunk * BK;
        const uint32_t sbase = sb + stage * STAGE_BYTES;
        // A: 128 rows x 64 k = 1024 cp16 (2 per thread)
        #pragma unroll
        for (int t = 0; t < 2; ++t) {
            int gi = tid + t * NTHREADS;            // 0..1023
            int r = gi >> 3, c8 = (gi & 7) * 8;
            cp16(sbase + (uint32_t)(r * TPAD + c8) * 2,
                 srcA + (size_t)(m0 + r) * 1024 + k0 + c8);
        }
        // B: 256 rows x 64 k = 2048 cp16 (4 per thread)
        #pragma unroll
        for (int t = 0; t < 4; ++t) {
            int gi = tid + t * NTHREADS;            // 0..2047
            int r = gi >> 3, c8 = (gi & 7) * 8;
            cp16(sbase + ATB + (uint32_t)(r * TPAD + c8) * 2,
                 srcB + (size_t)(n0 + r) * 1024 + k0 + c8);
        }
    };

    // prologue: stages 0,1
    load_chunk(0, 0);
    asm volatile("cp.async.commit_group;" ::: "memory");
    load_chunk(1, 1);
    asm volatile("cp.async.commit_group;" ::: "memory");

    float acc[2][8][4];
    #pragma unroll
    for (int mi = 0; mi < 2; ++mi)
        #pragma unroll
        for (int ni = 0; ni < 8; ++ni)
            #pragma unroll
            for (int e = 0; e < 4; ++e) acc[mi][ni][e] = 0.f;

    for (int c = 0; c < CHUNKS; ++c) {
        asm volatile("cp.async.wait_group 1;" ::: "memory");   // chunk c arrived
        __syncthreads();

        const int nc = c + STAGES - 1;
        if (nc < CHUNKS) load_chunk(nc, nc % STAGES);
        asm volatile("cp.async.commit_group;" ::: "memory");

        const uint32_t sbase = sb + (c % STAGES) * STAGE_BYTES;
        const uint32_t aB = sbase, bB = sbase + ATB;

        #pragma unroll
        for (int s16 = 0; s16 < 4; ++s16) {
            const int koff = s16 * 16;
            uint32_t ah[2][4];
            #pragma unroll
            for (int mi = 0; mi < 2; ++mi) {
                uint32_t ro = (uint32_t)((warp_m * 32 + mi * 16 + (lane & 15)) * TPAD) * 2
                            + (uint32_t)(koff + ((lane >> 4) << 3)) * 2;
                ldsm4(ah[mi], aB + ro);
            }
            #pragma unroll
            for (int nj = 0; nj < 4; ++nj) {
                uint32_t bh[4];
                uint32_t ro = (uint32_t)((warp_n * 64 + nj * 16 + (lane & 7) + ((lane >> 4) << 3)) * TPAD) * 2
                            + (uint32_t)(koff + (((lane >> 3) & 1) << 3)) * 2;
                ldsm4(bh, bB + ro);
                #pragma unroll
                for (int mi = 0; mi < 2; ++mi)
                    #pragma unroll
                    for (int half = 0; half < 2; ++half)
                        mma_f16(acc[mi][nj * 2 + half], ah[mi], &bh[half * 2]);
            }
        }
    }

    // ------------------------------ epilogue (all coalesced) ----------------
    const int erow = m0 + warp_m * 32;
    const int ecol = n0 + warp_n * 64;
    const int rl = lane >> 2, cl = (lane & 3) * 2;

    #pragma unroll
    for (int mi = 0; mi < 2; ++mi) {
        const int r0e = erow + mi * 16 + rl;           // rows r0e, r0e+8
        float b0 = 0.f, b1 = 0.f;
        if (EPI == EPI_TANH || EPI == EPI_BIASRES) {
            b0 = bias[r0e]; b1 = bias[r0e + 8];
        }
        #pragma unroll
        for (int ni = 0; ni < 8; ++ni) {
            const int c0e = ecol + ni * 8 + cl;
            float* a = acc[mi][ni];
            const size_t row0 = bat + (size_t)r0e * 1024 + c0e;
            const size_t row1 = bat + (size_t)(r0e + 8) * 1024 + c0e;

            if (EPI == EPI_TANH) {
                *(__half2*)(Oh + row0) = __floats2half2_rn(tanhf(a[0] + b0), tanhf(a[1] + b0));
                *(__half2*)(Oh + row1) = __floats2half2_rn(tanhf(a[2] + b1), tanhf(a[3] + b1));
            } else if (EPI == EPI_TANH_CB) {
                const float bc0 = bias[c0e], bc1 = bias[c0e + 1];
                *(__half2*)(Oh + row0) = __floats2half2_rn(tanhf(a[0] + bc0), tanhf(a[1] + bc1));
                *(__half2*)(Oh + row1) = __floats2half2_rn(tanhf(a[2] + bc0), tanhf(a[3] + bc1));
            } else if (EPI == EPI_CAST) {
                *(__half2*)(Oh + row0) = __floats2half2_rn(a[0], a[1]);
                *(__half2*)(Oh + row1) = __floats2half2_rn(a[2], a[3]);
            } else if (EPI == EPI_SCALE) {
                float2 o0{a[0] * alpha, a[1] * alpha};
                float2 o1{a[2] * alpha, a[3] * alpha};
                *(float2*)(Of + row0) = o0;
                *(float2*)(Of + row1) = o1;
            } else {  // EPI_BIASRES
                float2 r0v = *(const float2*)(resid + row0);
                float2 r1v = *(const float2*)(resid + row1);
                float2 o0{a[0] + b0 + r0v.x, a[1] + b0 + r0v.y};
                float2 o1{a[2] + b1 + r1v.x, a[3] + b1 + r1v.y};
                *(float2*)(Of + row0) = o0;
                *(float2*)(Of + row1) = o1;
            }
        }
    }
}

// ---------------------------------------------------------------------------
// fp32 -> fp16 elementwise (weights)
// ---------------------------------------------------------------------------
__global__ __launch_bounds__(256) void cast_k(const float* __restrict__ in,
                                              __half* __restrict__ o) {
    size_t i = ((size_t)blockIdx.x * 256 + threadIdx.x) * 4;
    float4 v = *(const float4*)(in + i);
    *(__half2*)(o + i)     = __floats2half2_rn(v.x, v.y);
    *(__half2*)(o + i + 2) = __floats2half2_rn(v.z, v.w);
}

// ---------------------------------------------------------------------------
// fp32 [B][C,S] -> transposed fp16 [B][S,C]
// ---------------------------------------------------------------------------
__global__ __launch_bounds__(256) void transpose_cast_k(
    const float* __restrict__ in, __half* __restrict__ o) {
    __shared__ float t[32][33];
    const int tx = threadIdx.x, ty = threadIdx.y;   // 32x8
    const int s0 = blockIdx.x * 32, c0 = blockIdx.y * 32;
    const size_t bat = (size_t)blockIdx.z * MAT;
    #pragma unroll
    for (int i = 0; i < 4; ++i)
        t[ty + 8 * i][tx] = in[bat + (size_t)(c0 + ty + 8 * i) * 1024 + s0 + tx];
    __syncthreads();
    #pragma unroll
    for (int i = 0; i < 4; ++i)
        o[bat + (size_t)(s0 + ty + 8 * i) * 1024 + c0 + tx] = __float2half(t[tx][ty + 8 * i]);
}

// ---------------------------------------------------------------------------
// Row softmax fp32 -> fp16 weights
// ---------------------------------------------------------------------------
__global__ __launch_bounds__(256) void softmax_cast_k(
    const float* __restrict__ data, __half* __restrict__ o) {
    __shared__ float red[8];
    __shared__ float bval;
    const size_t row = blockIdx.x;
    const float* p = data + row * (size_t)NC;
    const int tid = threadIdx.x, lane = tid & 31, wid = tid >> 5;

    float4 v = ((const float4*)p)[tid];
    float mx = fmaxf(fmaxf(v.x, v.y), fmaxf(v.z, v.w));
    #pragma unroll
    for (int off = 16; off > 0; off >>= 1) mx = fmaxf(mx, __shfl_xor_sync(0xffffffffu, mx, off));
    if (lane == 0) red[wid] = mx;
    __syncthreads();
    if (tid < 32) {
        float t = (tid < 8) ? red[tid] : -INFINITY;
        #pragma unroll
        for (int off = 4; off > 0; off >>= 1) t = fmaxf(t, __shfl_xor_sync(0xffffffffu, t, off));
        if (tid == 0) bval = t;
    }
    __syncthreads();
    mx = bval;
    v.x = expf(v.x - mx); v.y = expf(v.y - mx);
    v.z = expf(v.z - mx); v.w = expf(v.w - mx);
    float s = (v.x + v.y) + (v.z + v.w);
    #pragma unroll
    for (int off = 16; off > 0; off >>= 1) s += __shfl_xor_sync(0xffffffffu, s, off);
    __syncthreads();
    if (lane == 0) red[wid] = s;
    __syncthreads();
    if (tid < 32) {
        float t = (tid < 8) ? red[tid] : 0.f;
        #pragma unroll
        for (int off = 4; off > 0; off >>= 1) t += __shfl_xor_sync(0xffffffffu, t, off);
        if (tid == 0) bval = t;
    }
    __syncthreads();
    const float inv = 1.f / bval;
    const size_t base = row * (size_t)NC + 4 * tid;
    *(__half2*)(o + base)     = __floats2half2_rn(v.x * inv, v.y * inv);
    *(__half2*)(o + base + 2) = __floats2half2_rn(v.z * inv, v.w * inv);
}

// ---------------------------------------------------------------------------
extern "C" void kernel_launch(void* const* d_in, const int* in_sizes, int n_in,
                              void* d_out, int out_size)
{
    const float* shape_map = (const float*)d_in[0];
    const float* img_map   = (const float*)d_in[1];
    const float* wq = (const float*)d_in[2];
    const float* bq = (const float*)d_in[3];
    const float* wk = (const float*)d_in[4];
    const float* bk = (const float*)d_in[5];
    const float* wv = (const float*)d_in[6];
    const float* bv = (const float*)d_in[7];
    const float* wc = (const float*)d_in[8];
    const float* bc = (const float*)d_in[9];
    float* out = (float*)d_out;

    unsigned char* buf;
    cudaGetSymbolAddress((void**)&buf, g_buf);
    __half* XS  = (__half*)(buf + OFF_XS);
    __half* XI  = (__half*)(buf + OFF_XI);
    __half* Q   = (__half*)(buf + OFF_Q);
    __half* K   = (__half*)(buf + OFF_K);
    __half* VT  = (__half*)(buf + OFF_VT);
    __half* WA  = (__half*)(buf + OFF_WA);
    __half* NVT = (__half*)(buf + OFF_NVT);
    float*  SF  = (float*)(buf + OFF_SF32);
    __half* W[4];   // q,k,v,c
    for (int i = 0; i < 4; ++i) W[i] = (__half*)(buf + OFF_W0 + (size_t)i * 2 * MB1);

    cudaFuncSetAttribute(gemm_mma<EPI_TANH, false, true>,    cudaFuncAttributeMaxDynamicSharedMemorySize, SMEM_BYTES);
    cudaFuncSetAttribute(gemm_mma<EPI_TANH_CB, true, false>, cudaFuncAttributeMaxDynamicSharedMemorySize, SMEM_BYTES);
    cudaFuncSetAttribute(gemm_mma<EPI_SCALE, true, true>,    cudaFuncAttributeMaxDynamicSharedMemorySize, SMEM_BYTES);
    cudaFuncSetAttribute(gemm_mma<EPI_CAST, true, true>,     cudaFuncAttributeMaxDynamicSharedMemorySize, SMEM_BYTES);
    cudaFuncSetAttribute(gemm_mma<EPI_BIASRES, false, true>, cudaFuncAttributeMaxDynamicSharedMemorySize, SMEM_BYTES);

    const dim3 grid(4, 8, NB);   // n-tiles(256) x m-tiles(128) x batch

    // converts
    cast_k<<<MAT / 1024, 256>>>(wq, W[0]);
    cast_k<<<MAT / 1024, 256>>>(wk, W[1]);
    cast_k<<<MAT / 1024, 256>>>(wv, W[2]);
    cast_k<<<MAT / 1024, 256>>>(wc, W[3]);
    transpose_cast_k<<<dim3(32, 32, NB), dim3(32, 8)>>>(shape_map, XS);
    transpose_cast_k<<<dim3(32, 32, NB), dim3(32, 8)>>>(img_map, XI);

    // Q[c,s] = tanh(Wq@Xs + bq):  A=Wq [C,C], B=XS [S,C] batched -> [C,S]
    gemm_mma<EPI_TANH, false, true><<<grid, NTHREADS, SMEM_BYTES>>>(W[0], XS, bq, nullptr, nullptr, Q, 0.f);
    gemm_mma<EPI_TANH, false, true><<<grid, NTHREADS, SMEM_BYTES>>>(W[1], XI, bk, nullptr, nullptr, K, 0.f);
    // VT[s,c] = tanh(sum_d XI[s,d]*Wv[c,d] + bv[c]):  A=XI batched, B=Wv -> [S,C] coalesced
    gemm_mma<EPI_TANH_CB, true, false><<<grid, NTHREADS, SMEM_BYTES>>>(XI, W[2], bv, nullptr, nullptr, VT, 0.f);
    // scores[c,d] = (Q @ K^T)/32 -> fp32 [C,C]
    gemm_mma<EPI_SCALE, true, true><<<grid, NTHREADS, SMEM_BYTES>>>(Q, K, nullptr, nullptr, SF, nullptr, 0.03125f);
    // softmax rows -> fp16 weights
    softmax_cast_k<<<NB * NC, 256>>>(SF, WA);
    // NVT[s,c] = sum_d VT[s,d]*WA[c,d] = new_v^T -> [S,C] coalesced
    gemm_mma<EPI_CAST, true, true><<<grid, NTHREADS, SMEM_BYTES>>>(VT, WA, nullptr, nullptr, nullptr, NVT, 0.f);
    // out[c,s] = sum_d Wc[c,d]*NVT[s,d] + bc[c] + shape_map  -> fp32 [C,S]
    gemm_mma<EPI_BIASRES, false, true><<<grid, NTHREADS, SMEM_BYTES>>>(W[3], NVT, bc, shape_map, out, nullptr, 0.f);
}